// round 13
// baseline (speedup 1.0000x reference)
#include <cuda_runtime.h>
#include <cuda_fp16.h>
#include <cstdint>

#define N_NODES 10000
#define N_EDGES 160000
#define HID 256
#define NBOND 6
#define NATOM 62
#define NLAYERS 6
#define NSLOTS 26
#define NCOMB 22
#define NPC 8
#define CHE 32

// ---------------- scratch (device globals; no allocation allowed) ----------
__device__ float g_x[N_NODES * HID];    // x0 as __half
__device__ float g_xa[N_NODES * HID];   // xa as __half
__device__ float g_xb[N_NODES * HID];   // xb fp32 / final r2 fp32
__device__ float g_agg[N_NODES * HID];  // ragg as __half
__device__ float g_t1[N_NODES * HID];   // t1 fp32 / r1 as __half
__device__ float g_h[N_NODES * HID];    // h as __half

__device__ int   g_deg[N_NODES];
__device__ int   g_rowptr[N_NODES + 1];
__device__ int   g_cursor[N_NODES];
__device__ int   g_ssrc[N_EDGES];
__device__ float g_sef[N_EDGES * NBOND];
__device__ float g_degf[N_NODES];

__device__ float g_wcomb[NCOMB * 65536];
__device__ float g_vbias[NCOMB * 256];
__device__ __half g_wt[NSLOTS * 256 * 256];

// software global barrier state
__device__ unsigned g_count = 0;
__device__ unsigned g_gen = 0;

// ---------------- helpers ---------------------------------------------------
__device__ __forceinline__ uint32_t smem_u32(const void* p) {
    uint32_t a;
    asm("{ .reg .u64 t; cvta.to.shared.u64 t, %1; cvt.u32.u64 %0, t; }"
        : "=r"(a) : "l"(p));
    return a;
}
__device__ __forceinline__ void ldm_x4(uint32_t* r, uint32_t addr) {
    asm volatile("ldmatrix.sync.aligned.m8n8.x4.shared.b16 {%0,%1,%2,%3}, [%4];"
                 : "=r"(r[0]), "=r"(r[1]), "=r"(r[2]), "=r"(r[3]) : "r"(addr));
}
__device__ __forceinline__ void mma_f16(float* c, const uint32_t* a,
                                        uint32_t b0, uint32_t b1) {
    asm volatile(
        "mma.sync.aligned.m16n8k16.row.col.f32.f16.f16.f32 "
        "{%0,%1,%2,%3}, {%4,%5,%6,%7}, {%8,%9}, {%0,%1,%2,%3};"
        : "+f"(c[0]), "+f"(c[1]), "+f"(c[2]), "+f"(c[3])
        : "r"(a[0]), "r"(a[1]), "r"(a[2]), "r"(a[3]), "r"(b0), "r"(b1));
}
__device__ __forceinline__ void cp16(uint32_t dst, const void* src) {
    asm volatile("cp.async.cg.shared.global [%0], [%1], 16;"
                 :: "r"(dst), "l"(src));
}
__device__ __forceinline__ void cp_commit() {
    asm volatile("cp.async.commit_group;" ::: "memory");
}
__device__ __forceinline__ void cp_wait0() {
    asm volatile("cp.async.wait_group 0;" ::: "memory");
}

// grid-wide barrier: all CTAs resident (grid sized via occupancy API).
// threadfence after resolution invalidates L1D (gpu-scope) for fresh reads.
__device__ __forceinline__ void gsync() {
    __syncthreads();
    if (threadIdx.x == 0) {
        __threadfence();
        unsigned gen = *(volatile unsigned*)&g_gen;
        if (atomicAdd(&g_count, 1u) == gridDim.x - 1) {
            g_count = 0;
            __threadfence();
            *(volatile unsigned*)&g_gen = gen + 1;
        } else {
            while (*(volatile unsigned*)&g_gen == gen) __nanosleep(64);
        }
        __threadfence();
    }
    __syncthreads();
}

// ---------------------------------------------------------------------------
// Combo source pointers (setup)
// ---------------------------------------------------------------------------
__device__ __forceinline__ const float* combo_Q(
    int c, const float* mw1, const float* uw1, const float* rw1)
{
    if (c < 6) return uw1 + (size_t)c * 131072 + 65536;
    if (c < 21) {
        int m = (c - 6) / 3, t = (c - 6) % 3;
        int l = m + 1;
        if (t == 0) return mw1 + (size_t)l * 518 * 256;
        if (t == 1) return mw1 + (size_t)l * 518 * 256 + 65536;
        return uw1 + (size_t)l * 131072;
    }
    return rw1;
}

__global__ void __launch_bounds__(256) combine_kernel(
    const float* __restrict__ mw1, const float* __restrict__ uw1,
    const float* __restrict__ mw2, const float* __restrict__ uw2,
    const float* __restrict__ rw1)
{
    int c = blockIdx.z;
    const float* P = (c < 6) ? mw2 + (size_t)c * 65536
                   : (c < 21) ? uw2 + (size_t)((c - 6) / 3) * 65536
                              : uw2 + (size_t)5 * 65536;
    const float* Q = combo_Q(c, mw1, uw1, rw1);
    float* C = g_wcomb + (size_t)c * 65536;

    __shared__ float As[16][128];
    __shared__ float Ws[16][128];
    int col0 = blockIdx.x * 128, row0 = blockIdx.y * 128;
    int tid = threadIdx.x;
    int tx = tid & 15, ty = tid >> 4;

    float acc[8][8];
#pragma unroll
    for (int i = 0; i < 8; i++)
#pragma unroll
        for (int j = 0; j < 8; j++) acc[i][j] = 0.f;

    int ar = tid >> 2, ac = (tid & 3) << 2;
    int wr = tid >> 5, wc = (tid & 31) << 2;

    for (int kt = 0; kt < 256; kt += 16) {
#pragma unroll
        for (int i = 0; i < 2; i++) {
            int r = ar + i * 64;
            float4 v = *(const float4*)(P + (size_t)(row0 + r) * 256 + kt + ac);
            As[ac + 0][r] = v.x; As[ac + 1][r] = v.y;
            As[ac + 2][r] = v.z; As[ac + 3][r] = v.w;
        }
#pragma unroll
        for (int i = 0; i < 2; i++) {
            int r = wr + i * 8;
            *(float4*)&Ws[r][wc] =
                *(const float4*)(Q + (size_t)(kt + r) * 256 + col0 + wc);
        }
        __syncthreads();
#pragma unroll
        for (int kk = 0; kk < 16; kk++) {
            float4 a0 = *(const float4*)&As[kk][ty * 4];
            float4 a1 = *(const float4*)&As[kk][64 + ty * 4];
            float4 w0 = *(const float4*)&Ws[kk][tx * 4];
            float4 w1 = *(const float4*)&Ws[kk][64 + tx * 4];
            float af[8] = {a0.x, a0.y, a0.z, a0.w, a1.x, a1.y, a1.z, a1.w};
            float wf[8] = {w0.x, w0.y, w0.z, w0.w, w1.x, w1.y, w1.z, w1.w};
#pragma unroll
            for (int i = 0; i < 8; i++)
#pragma unroll
                for (int j = 0; j < 8; j++)
                    acc[i][j] = fmaf(af[i], wf[j], acc[i][j]);
        }
        __syncthreads();
    }
#pragma unroll
    for (int ih = 0; ih < 2; ih++)
#pragma unroll
        for (int i = 0; i < 4; i++) {
            int r = row0 + ih * 64 + ty * 4 + i;
#pragma unroll
            for (int jh = 0; jh < 2; jh++)
#pragma unroll
                for (int j = 0; j < 4; j++)
                    C[(size_t)r * 256 + col0 + jh * 64 + tx * 4 + j] =
                        acc[ih * 4 + i][jh * 4 + j];
        }
}

__global__ void __launch_bounds__(256) vbias_kernel(
    const float* __restrict__ mw1, const float* __restrict__ uw1,
    const float* __restrict__ rw1, const float* __restrict__ mb2,
    const float* __restrict__ ub2, const float* __restrict__ rb1)
{
    int c = blockIdx.x;
    const float* b = (c < 6) ? mb2 + (size_t)c * 256
                   : (c < 21) ? ub2 + (size_t)((c - 6) / 3) * 256
                              : ub2 + (size_t)5 * 256;
    const float* Q = combo_Q(c, mw1, uw1, rw1);
    int n = threadIdx.x;
    float s = 0.f;
    for (int k = 0; k < 256; k++) s = fmaf(b[k], Q[(size_t)k * 256 + n], s);
    if (c == 21) s += rb1[n];
    g_vbias[(size_t)c * 256 + n] = s;
}

__global__ void wsplit_kernel(
    const float* __restrict__ mw1, const float* __restrict__ uw1,
    const float* __restrict__ rw2, __half* __restrict__ wt)
{
    int z = blockIdx.z;
    const float* W;
    int N = 256;
    if (z < 2)       W = mw1 + (size_t)z * 65536;
    else if (z == 2) W = uw1;
    else if (z < 25) W = g_wcomb + (size_t)(z - 3) * 65536;
    else { W = rw2; N = 128; }

    int k0 = blockIdx.x * 32, n0 = blockIdx.y * 32;
    if (n0 >= N) return;
    __shared__ float t[32][33];
    for (int i = threadIdx.y; i < 32; i += 8)
        t[i][threadIdx.x] = W[(size_t)(k0 + i) * N + n0 + threadIdx.x];
    __syncthreads();
    size_t base = (size_t)z * 65536;
    for (int i = threadIdx.y; i < 32; i += 8)
        wt[base + (size_t)(n0 + i) * 256 + k0 + threadIdx.x] =
            __float2half(t[threadIdx.x][i]);
}

// ---------------------------------------------------------------------------
// Embed (standalone, overlaps setup): x0 = fp16(atom @ embed_w + embed_b)
// ---------------------------------------------------------------------------
#define EMB_NODES 16
__global__ void __launch_bounds__(256) embed_kernel(
    const float* __restrict__ atom, const float* __restrict__ w,
    const float* __restrict__ b, __half* __restrict__ x16)
{
    __shared__ float s_af[EMB_NODES][NATOM];
    int n0 = blockIdx.x * EMB_NODES;
    int tid = threadIdx.x;
    for (int i = tid; i < EMB_NODES * NATOM; i += 256) {
        int r = i / NATOM, c = i % NATOM;
        int n = n0 + r;
        s_af[r][c] = (n < N_NODES) ? atom[(size_t)n * NATOM + c] : 0.f;
    }
    __syncthreads();
    int j = tid;
    float acc[EMB_NODES];
    float bj = b[j];
#pragma unroll
    for (int r = 0; r < EMB_NODES; r++) acc[r] = bj;
    for (int k = 0; k < NATOM; k++) {
        float wv = w[k * HID + j];
#pragma unroll
        for (int r = 0; r < EMB_NODES; r++) acc[r] = fmaf(s_af[r][k], wv, acc[r]);
    }
#pragma unroll
    for (int r = 0; r < EMB_NODES; r++) {
        int n = n0 + r;
        if (n < N_NODES) x16[(size_t)n * HID + j] = __float2half(acc[r]);
    }
}

// ---------------------------------------------------------------------------
// CSR build
// ---------------------------------------------------------------------------
__global__ void count_kernel(const int* __restrict__ dst)
{
    int e = blockIdx.x * blockDim.x + threadIdx.x;
    if (e < N_EDGES) atomicAdd(&g_deg[dst[e]], 1);
}

__global__ void __launch_bounds__(1024) scan_kernel()
{
    __shared__ int sdeg[10240];
    __shared__ int warpsum[32];
    int tid = threadIdx.x;
#pragma unroll
    for (int i = 0; i < 10; i++) {
        int idx = i * 1024 + tid;
        sdeg[idx] = (idx < N_NODES) ? g_deg[idx] : 0;
    }
    __syncthreads();
    int base = tid * 10;
    int v[10];
    int tot = 0;
#pragma unroll
    for (int i = 0; i < 10; i++) {
        v[i] = sdeg[base + i];
        tot += v[i];
    }
    int lane = tid & 31, wid = tid >> 5;
    int x = tot;
#pragma unroll
    for (int off = 1; off < 32; off <<= 1) {
        int y = __shfl_up_sync(~0u, x, off);
        if (lane >= off) x += y;
    }
    if (lane == 31) warpsum[wid] = x;
    __syncthreads();
    if (wid == 0) {
        int w = warpsum[lane];
#pragma unroll
        for (int off = 1; off < 32; off <<= 1) {
            int y = __shfl_up_sync(~0u, w, off);
            if (lane >= off) w += y;
        }
        warpsum[lane] = w;
    }
    __syncthreads();
    int run = x - tot + (wid ? warpsum[wid - 1] : 0);
    if (tid == 0) g_rowptr[0] = 0;
#pragma unroll
    for (int i = 0; i < 10; i++) {
        int idx = base + i;
        if (idx < N_NODES) {
            g_cursor[idx] = run;
            run += v[i];
            g_rowptr[idx + 1] = run;
            g_degf[idx] = (float)v[i];
        }
    }
}

__global__ void fill_kernel(const int* __restrict__ src,
                            const int* __restrict__ dst,
                            const float* __restrict__ ef)
{
    int e = blockIdx.x * blockDim.x + threadIdx.x;
    if (e >= N_EDGES) return;
    int d = dst[e];
    int pos = atomicAdd(&g_cursor[d], 1);
    g_ssrc[pos] = src[e];
#pragma unroll
    for (int q = 0; q < NBOND; q++)
        g_sef[(size_t)pos * NBOND + q] = ef[(size_t)e * NBOND + q];
}

// ---------------------------------------------------------------------------
// Persistent-kernel stages
// ---------------------------------------------------------------------------
// GEMM stage: tiles 128x128 (MI=4), 1-term fp16, cp.async double-buffered.
// flags: 1=RELU 2=ADDC 4=BIAS 8=ROWB 16=HALF_OUT(bz0)
__device__ __noinline__ void gemm_stage(
    const __half* __restrict__ A, const __half* __restrict__ wt,
    int s0, int s1, int s2, int nz, int ncol,
    const float* b0p, const float* b1p, const float* b2p,
    const float* rbias, const float* rowscale, const float* Cprev,
    float* C0, float* C1, float* C2,
    int ldc, int flags, char* smem)
{
    const int ROWT = (N_NODES + 127) / 128;  // 79
    const int WBASE = 128 * 80;              // 10240
    const int BUFSZ = WBASE + 10240;         // 20480

    uint32_t sb = smem_u32(smem);
    int tid = threadIdx.x;
    int lane = tid & 31, wid = tid >> 5;
    int wr = wid >> 2, wc = wid & 3;

    int a_row = lane & 15;
    int a_kh = (lane >> 4) * 8;
    int bg = lane >> 3;
    int b_n = (lane & 7) + (bg >> 1) * 8;
    int b_kh = (bg & 1) * 8;

    int lrow = tid >> 1;
    int lhalf = tid & 1;
    uint32_t wsoff = (uint32_t)(lrow * 80 + lhalf * 32);

    int total = ncol * ROWT * nz;
    for (int t = blockIdx.x; t < total; t += gridDim.x) {
        int bz = t / (ncol * ROWT);
        int rem = t - bz * ncol * ROWT;
        int by = rem / ncol, bxc = rem - by * ncol;
        int row0 = by * 128, col0 = bxc * 128;

        int slot = (bz == 0) ? s0 : (bz == 1 ? s1 : s2);
        float* C = (bz == 0) ? C0 : (bz == 1 ? C1 : C2);
        const float* bias = (bz == 0) ? b0p : (bz == 1 ? b1p : b2p);
        const __half* Wp = wt + (size_t)slot * 65536;
        bool half_out = (flags & 16) && (bz == 0);
        size_t wgoff = (size_t)(col0 + lrow) * 256 + lhalf * 16;

        float acc[4][4][4];
#pragma unroll
        for (int i = 0; i < 4; i++)
#pragma unroll
            for (int j = 0; j < 4; j++)
#pragma unroll
                for (int k = 0; k < 4; k++) acc[i][j][k] = 0.f;

#define ISSUE_AW(ch, buf)                                                   \
    do {                                                                    \
        uint32_t bb_ = sb + (buf) * BUFSZ;                                  \
        for (int idx = tid; idx < 512; idx += 256) {                        \
            int r_ = idx >> 2, seg_ = idx & 3;                              \
            cp16(bb_ + (uint32_t)(r_ * 80 + seg_ * 16),                     \
                 A + (size_t)(row0 + r_) * 256 + (ch) * 32 + seg_ * 8);     \
        }                                                                   \
        const __half* pw_ = Wp + wgoff + (ch) * 32;                         \
        cp16(bb_ + WBASE + wsoff, pw_);                                     \
        cp16(bb_ + WBASE + wsoff + 16, pw_ + 8);                            \
    } while (0)

        ISSUE_AW(0, 0);
        cp_commit();
        cp_wait0();
        __syncthreads();

#pragma unroll 2
        for (int ch = 0; ch < 8; ch++) {
            int buf = ch & 1;
            if (ch < 7) {
                ISSUE_AW(ch + 1, buf ^ 1);
                cp_commit();
            }
            uint32_t base = sb + buf * BUFSZ;
#pragma unroll
            for (int ks = 0; ks < 2; ks++) {
                uint32_t Af[4][4], Bf[2][4];
                uint32_t acol = (uint32_t)((ks * 16 + a_kh) * 2);
                uint32_t bcol = (uint32_t)((ks * 16 + b_kh) * 2);
#pragma unroll
                for (int nj = 0; nj < 2; nj++)
                    ldm_x4(Bf[nj], base + WBASE +
                           (uint32_t)((wc * 32 + nj * 16 + b_n) * 80) + bcol);
#pragma unroll
                for (int mi = 0; mi < 4; mi++)
                    ldm_x4(Af[mi], base +
                           (uint32_t)((wr * 64 + mi * 16 + a_row) * 80) + acol);
#pragma unroll
                for (int mi = 0; mi < 4; mi++)
#pragma unroll
                    for (int ni = 0; ni < 4; ni++) {
                        int nj = ni >> 1, off = (ni & 1) * 2;
                        mma_f16(acc[mi][ni], Af[mi], Bf[nj][off],
                                Bf[nj][off + 1]);
                    }
            }
            if (ch < 7) {
                cp_wait0();
                __syncthreads();
            }
        }

        // epilogue
#pragma unroll
        for (int mi = 0; mi < 4; mi++) {
            int m0 = row0 + wr * 64 + mi * 16 + (lane >> 2);
            int m1 = m0 + 8;
            float rs0 = 0.f, rs1 = 0.f;
            if (flags & 8) {
                if (m0 < N_NODES) rs0 = rowscale[m0];
                if (m1 < N_NODES) rs1 = rowscale[m1];
            }
#pragma unroll
            for (int ni = 0; ni < 4; ni++) {
                int nc = col0 + wc * 32 + ni * 8 + (lane & 3) * 2;
                float b0 = 0.f, b1 = 0.f, r0b = 0.f, r1b = 0.f;
                if (flags & 4) { b0 = bias[nc]; b1 = bias[nc + 1]; }
                if (flags & 8) { r0b = rbias[nc]; r1b = rbias[nc + 1]; }
                float* a = acc[mi][ni];
                if (m0 < N_NODES) {
                    float v0 = a[0] + b0, v1 = a[1] + b1;
                    if (flags & 8) { v0 = fmaf(rs0, r0b, v0);
                                     v1 = fmaf(rs0, r1b, v1); }
                    if (flags & 2) {
                        v0 += Cprev[(size_t)m0 * 256 + nc];
                        v1 += Cprev[(size_t)m0 * 256 + nc + 1];
                    }
                    if (flags & 1) { v0 = fmaxf(v0, 0.f); v1 = fmaxf(v1, 0.f); }
                    if (half_out)
                        *(__half2*)((__half*)C + (size_t)m0 * ldc + nc) =
                            __floats2half2_rn(v0, v1);
                    else
                        *(float2*)(C + (size_t)m0 * ldc + nc) =
                            make_float2(v0, v1);
                }
                if (m1 < N_NODES) {
                    float v0 = a[2] + b0, v1 = a[3] + b1;
                    if (flags & 8) { v0 = fmaf(rs1, r0b, v0);
                                     v1 = fmaf(rs1, r1b, v1); }
                    if (flags & 2) {
                        v0 += Cprev[(size_t)m1 * 256 + nc];
                        v1 += Cprev[(size_t)m1 * 256 + nc + 1];
                    }
                    if (flags & 1) { v0 = fmaxf(v0, 0.f); v1 = fmaxf(v1, 0.f); }
                    if (half_out)
                        *(__half2*)((__half*)C + (size_t)m1 * ldc + nc) =
                            __floats2half2_rn(v0, v1);
                    else
                        *(float2*)(C + (size_t)m1 * ldc + nc) =
                            make_float2(v0, v1);
                }
            }
        }
        __syncthreads();  // smem reuse guard before next tile
#undef ISSUE_AW
    }
}

// aggregate stage: ragg16[n] = fp16( sum relu(xa16[src]+xb[n]+ef@W1c+b1) )
__device__ __noinline__ void aggregate_stage(
    const __half* __restrict__ xa16, const float* __restrict__ xb,
    const float* __restrict__ w1c, const float* __restrict__ b1,
    __half* __restrict__ ragg16, char* smem)
{
    int* s_src = (int*)smem;
    float (*s_ef)[NBOND] = (float (*)[NBOND])(smem + CHE * sizeof(int));

    int c = threadIdx.x;
    float wreg[NBOND];
#pragma unroll
    for (int q = 0; q < NBOND; q++) wreg[q] = w1c[q * 256 + c];
    float b1c = b1[c];

    const int NBLK = (N_NODES + NPC - 1) / NPC;
    for (int nb = blockIdx.x; nb < NBLK; nb += gridDim.x) {
        int n0 = nb * NPC;
        for (int ni = 0; ni < NPC; ni++) {
            int n = n0 + ni;
            if (n >= N_NODES) break;
            float base_v = b1c + xb[(size_t)n * HID + c];
            int beg = g_rowptr[n], end = g_rowptr[n + 1];
            float acc = 0.f;
            for (int b0 = beg; b0 < end; b0 += CHE) {
                int m = min(CHE, end - b0);
                __syncthreads();
                if (c < m) s_src[c] = g_ssrc[b0 + c];
                if (c < m * NBOND)
                    s_ef[c / NBOND][c % NBOND] = g_sef[(size_t)b0 * NBOND + c];
                __syncthreads();
                for (int j = 0; j < m; j++) {
                    float t = base_v +
                              __half2float(xa16[(size_t)s_src[j] * HID + c]);
#pragma unroll
                    for (int q = 0; q < NBOND; q++)
                        t = fmaf(s_ef[j][q], wreg[q], t);
                    acc += fmaxf(t, 0.f);
                }
            }
            ragg16[(size_t)n * HID + c] = __float2half(acc);
        }
        __syncthreads();
    }
}

// final reduce: out = mean_n( r2[n,:] . w3 + b3 )
__device__ void final_stage(const float* __restrict__ r2,
                            const float* __restrict__ w3,
                            const float* __restrict__ b3,
                            float* out, char* smem)
{
    float* sred = (float*)smem;
    float part = 0.f;
    float b3v = b3[0];
    for (int n = blockIdx.x * 256 + threadIdx.x; n < N_NODES;
         n += gridDim.x * 256) {
        const float* row = r2 + (size_t)n * 128;
        float s = 0.f;
#pragma unroll
        for (int k = 0; k < 128; k += 4) {
            float4 rv = *(const float4*)(row + k);
            float4 wv = *(const float4*)(w3 + k);
            s += rv.x * wv.x + rv.y * wv.y + rv.z * wv.z + rv.w * wv.w;
        }
        part += (s + b3v) * (1.0f / N_NODES);
    }
    sred[threadIdx.x] = part;
    __syncthreads();
    for (int st = 128; st > 0; st >>= 1) {
        if (threadIdx.x < st) sred[threadIdx.x] += sred[threadIdx.x + st];
        __syncthreads();
    }
    if (threadIdx.x == 0) atomicAdd(out, sred[0]);
}

struct MainParams {
    const float* mw1;
    const float* mb1;
    const float* ub1;
    const float* rb2;
    const float* rw3;
    const float* rb3;
    float* out;
};

__global__ void __launch_bounds__(256, 2) mpnn_main(MainParams p)
{
    extern __shared__ __align__(16) char smem[];
    if (blockIdx.x == 0 && threadIdx.x == 0) *p.out = 0.f;

    // xa,xb,t1 from x0(fp16)
    gemm_stage((const __half*)g_x, g_wt, 0, 1, 2, 3, 2,
               nullptr, nullptr, nullptr, nullptr, nullptr, nullptr,
               g_xa, g_xb, g_t1, 256, 16, smem);
    gsync();

    for (int l = 0; l < NLAYERS; l++) {
        const float* W1c = p.mw1 + (size_t)l * 518 * HID + 512 * HID;
        aggregate_stage((const __half*)g_xa, g_xb, W1c, p.mb1 + l * HID,
                        (__half*)g_agg, smem);
        gsync();

        gemm_stage((const __half*)g_agg, g_wt, 3 + l, 0, 0, 1, 2,
                   p.ub1 + l * HID, nullptr, nullptr,
                   g_vbias + (size_t)l * 256, g_degf, g_t1,
                   g_h, nullptr, nullptr, 256, 1 | 2 | 4 | 8 | 16, smem);
        gsync();

        if (l < NLAYERS - 1) {
            int cb = 6 + 3 * l;
            gemm_stage((const __half*)g_h, g_wt,
                       9 + 3 * l, 10 + 3 * l, 11 + 3 * l, 3, 2,
                       g_vbias + (size_t)cb * 256,
                       g_vbias + (size_t)(cb + 1) * 256,
                       g_vbias + (size_t)(cb + 2) * 256,
                       nullptr, nullptr, nullptr,
                       g_xa, g_xb, g_t1, 256, 4 | 16, smem);
            gsync();
        }
    }

    // r1(fp16) = relu(h@(U2_5@rw1) + vb21)
    gemm_stage((const __half*)g_h, g_wt, 24, 0, 0, 1, 2,
               g_vbias + (size_t)21 * 256, nullptr, nullptr,
               nullptr, nullptr, nullptr,
               g_t1, nullptr, nullptr, 256, 1 | 4 | 16, smem);
    gsync();
    // r2(fp32) = relu(r1@rw2 + rb2), N=128
    gemm_stage((const __half*)g_t1, g_wt, 25, 0, 0, 1, 1,
               p.rb2, nullptr, nullptr, nullptr, nullptr, nullptr,
               g_xb, nullptr, nullptr, 128, 1 | 4, smem);
    gsync();

    final_stage(g_xb, p.rw3, p.rb3, p.out, smem);
}

// ---------------------------------------------------------------------------
// Launch
// ---------------------------------------------------------------------------
extern "C" void kernel_launch(void* const* d_in, const int* in_sizes, int n_in,
                              void* d_out, int out_size)
{
    const float* atom = (const float*)d_in[0];
    const int*   eidx = (const int*)d_in[1];
    const float* ef   = (const float*)d_in[2];
    const float* embw = (const float*)d_in[3];
    const float* embb = (const float*)d_in[4];
    const float* mw1  = (const float*)d_in[5];
    const float* mb1  = (const float*)d_in[6];
    const float* mw2  = (const float*)d_in[7];
    const float* mb2  = (const float*)d_in[8];
    const float* uw1  = (const float*)d_in[9];
    const float* ub1  = (const float*)d_in[10];
    const float* uw2  = (const float*)d_in[11];
    const float* ub2  = (const float*)d_in[12];
    const float* rw1  = (const float*)d_in[13];
    const float* rb1  = (const float*)d_in[14];
    const float* rw2  = (const float*)d_in[15];
    const float* rb2  = (const float*)d_in[16];
    const float* rw3  = (const float*)d_in[17];
    const float* rb3  = (const float*)d_in[18];

    const int* src = eidx;
    const int* dst = eidx + N_EDGES;

    float* px;
    int* pdeg;
    __half* pwt;
    cudaGetSymbolAddress((void**)&px,  g_x);
    cudaGetSymbolAddress((void**)&pdeg, g_deg);
    cudaGetSymbolAddress((void**)&pwt, g_wt);

    const int MAIN_SMEM = 40960;
    static int nblocks = 0;
    if (!nblocks) {
        cudaFuncSetAttribute(mpnn_main,
                             cudaFuncAttributeMaxDynamicSharedMemorySize,
                             MAIN_SMEM);
        int per_sm = 0;
        cudaOccupancyMaxActiveBlocksPerMultiprocessor(&per_sm, mpnn_main, 256,
                                                      MAIN_SMEM);
        if (per_sm < 1) per_sm = 1;
        int dev = 0, sms = 0;
        cudaGetDevice(&dev);
        cudaDeviceGetAttribute(&sms, cudaDevAttrMultiProcessorCount, dev);
        nblocks = per_sm * sms;
    }

    static bool inited = false;
    static cudaStream_t sA, sB;
    static cudaEvent_t evRoot, evA, evB;
    if (!inited) {
        cudaStreamCreateWithFlags(&sA, cudaStreamNonBlocking);
        cudaStreamCreateWithFlags(&sB, cudaStreamNonBlocking);
        cudaEventCreateWithFlags(&evRoot, cudaEventDisableTiming);
        cudaEventCreateWithFlags(&evA, cudaEventDisableTiming);
        cudaEventCreateWithFlags(&evB, cudaEventDisableTiming);
        inited = true;
    }

    // fork
    cudaEventRecord(evRoot, 0);
    cudaStreamWaitEvent(sA, evRoot, 0);
    cudaStreamWaitEvent(sB, evRoot, 0);

    // stream A: weight pipeline
    combine_kernel<<<dim3(2, 2, NCOMB), 256, 0, sA>>>(mw1, uw1, mw2, uw2, rw1);
    vbias_kernel<<<NCOMB, 256, 0, sA>>>(mw1, uw1, rw1, mb2, ub2, rb1);
    wsplit_kernel<<<dim3(8, 8, NSLOTS), dim3(32, 8), 0, sA>>>(mw1, uw1, rw2, pwt);
    cudaEventRecord(evA, sA);

    // stream B: CSR pipeline
    cudaMemsetAsync(pdeg, 0, sizeof(int) * N_NODES, sB);
    count_kernel<<<(N_EDGES + 255) / 256, 256, 0, sB>>>(dst);
    scan_kernel<<<1, 1024, 0, sB>>>();
    fill_kernel<<<(N_EDGES + 255) / 256, 256, 0, sB>>>(src, dst, ef);
    cudaEventRecord(evB, sB);

    // main stream: embed (overlaps setup), then join both pipelines
    embed_kernel<<<(N_NODES + EMB_NODES - 1) / EMB_NODES, 256>>>(
        atom, embw, embb, (__half*)px);
    cudaStreamWaitEvent(0, evA, 0);
    cudaStreamWaitEvent(0, evB, 0);

    MainParams p;
    p.mw1 = mw1; p.mb1 = mb1; p.ub1 = ub1;
    p.rb2 = rb2; p.rw3 = rw3; p.rb3 = rb3;
    p.out = (float*)d_out;
    mpnn_main<<<nblocks, 256, MAIN_SMEM>>>(p);
}

// round 15
// speedup vs baseline: 1.2764x; 1.2764x over previous
#include <cuda_runtime.h>
#include <cuda_fp16.h>
#include <cstdint>

#define N_NODES 10000
#define N_EDGES 160000
#define HID 256
#define NBOND 6
#define NATOM 62
#define NLAYERS 6
#define NSLOTS 26
#define NCOMB 22

// ---------------- scratch (device globals; no allocation allowed) ----------
__device__ float g_x[N_NODES * HID];    // x0 as __half
__device__ float g_xa[N_NODES * HID];   // xa as __half
__device__ float g_xb[N_NODES * HID];   // xb fp32 / final r2 fp32
__device__ float g_agg[N_NODES * HID];  // ragg as __half
__device__ float g_t1[N_NODES * HID];   // t1 fp32 / r1 as __half
__device__ float g_h[N_NODES * HID];    // h as __half

__device__ int   g_deg[N_NODES];
__device__ int   g_rowptr[N_NODES + 1];
__device__ int   g_cursor[N_NODES];
__device__ int   g_ssrc[N_EDGES];
__device__ float g_sef[N_EDGES * NBOND];
__device__ float g_degf[N_NODES];

__device__ float g_wcomb[NCOMB * 65536];
__device__ float g_vbias[NCOMB * 256];
__device__ __half g_wt[NSLOTS * 256 * 256];

// ---------------- helpers ---------------------------------------------------
__device__ __forceinline__ uint32_t smem_u32(const void* p) {
    uint32_t a;
    asm("{ .reg .u64 t; cvta.to.shared.u64 t, %1; cvt.u32.u64 %0, t; }"
        : "=r"(a) : "l"(p));
    return a;
}
__device__ __forceinline__ void ldm_x4(uint32_t* r, uint32_t addr) {
    asm volatile("ldmatrix.sync.aligned.m8n8.x4.shared.b16 {%0,%1,%2,%3}, [%4];"
                 : "=r"(r[0]), "=r"(r[1]), "=r"(r[2]), "=r"(r[3]) : "r"(addr));
}
__device__ __forceinline__ void mma_f16(float* c, const uint32_t* a,
                                        uint32_t b0, uint32_t b1) {
    asm volatile(
        "mma.sync.aligned.m16n8k16.row.col.f32.f16.f16.f32 "
        "{%0,%1,%2,%3}, {%4,%5,%6,%7}, {%8,%9}, {%0,%1,%2,%3};"
        : "+f"(c[0]), "+f"(c[1]), "+f"(c[2]), "+f"(c[3])
        : "r"(a[0]), "r"(a[1]), "r"(a[2]), "r"(a[3]), "r"(b0), "r"(b1));
}
__device__ __forceinline__ void cp16(uint32_t dst, const void* src) {
    asm volatile("cp.async.cg.shared.global [%0], [%1], 16;"
                 :: "r"(dst), "l"(src));
}
__device__ __forceinline__ void cp_commit() {
    asm volatile("cp.async.commit_group;" ::: "memory");
}
__device__ __forceinline__ void cp_wait0() {
    asm volatile("cp.async.wait_group 0;" ::: "memory");
}

// ---------------------------------------------------------------------------
// Combo source pointers:
//  c in [0,6):   P = W2_l (mw2),  Q = U1b_l          (WU_l = W2@U1b)
//  c in [6,21):  P = U2_m (uw2),  Q in {W1a,W1b,U1a} of layer m+1
//  c == 21:      P = U2_5,        Q = rw1
// ---------------------------------------------------------------------------
__device__ __forceinline__ const float* combo_Q(
    int c, const float* mw1, const float* uw1, const float* rw1)
{
    if (c < 6) return uw1 + (size_t)c * 131072 + 65536;
    if (c < 21) {
        int m = (c - 6) / 3, t = (c - 6) % 3;
        int l = m + 1;
        if (t == 0) return mw1 + (size_t)l * 518 * 256;
        if (t == 1) return mw1 + (size_t)l * 518 * 256 + 65536;
        return uw1 + (size_t)l * 131072;
    }
    return rw1;
}

// fp32 setup GEMM: g_wcomb[c] = P_c @ Q_c   (256x256x256), grid (2,2,22)
__global__ void __launch_bounds__(256) combine_kernel(
    const float* __restrict__ mw1, const float* __restrict__ uw1,
    const float* __restrict__ mw2, const float* __restrict__ uw2,
    const float* __restrict__ rw1)
{
    int c = blockIdx.z;
    const float* P = (c < 6) ? mw2 + (size_t)c * 65536
                   : (c < 21) ? uw2 + (size_t)((c - 6) / 3) * 65536
                              : uw2 + (size_t)5 * 65536;
    const float* Q = combo_Q(c, mw1, uw1, rw1);
    float* C = g_wcomb + (size_t)c * 65536;

    __shared__ float As[16][128];
    __shared__ float Ws[16][128];
    int col0 = blockIdx.x * 128, row0 = blockIdx.y * 128;
    int tid = threadIdx.x;
    int tx = tid & 15, ty = tid >> 4;

    float acc[8][8];
#pragma unroll
    for (int i = 0; i < 8; i++)
#pragma unroll
        for (int j = 0; j < 8; j++) acc[i][j] = 0.f;

    int ar = tid >> 2, ac = (tid & 3) << 2;
    int wr = tid >> 5, wc = (tid & 31) << 2;

    for (int kt = 0; kt < 256; kt += 16) {
#pragma unroll
        for (int i = 0; i < 2; i++) {
            int r = ar + i * 64;
            float4 v = *(const float4*)(P + (size_t)(row0 + r) * 256 + kt + ac);
            As[ac + 0][r] = v.x; As[ac + 1][r] = v.y;
            As[ac + 2][r] = v.z; As[ac + 3][r] = v.w;
        }
#pragma unroll
        for (int i = 0; i < 2; i++) {
            int r = wr + i * 8;
            *(float4*)&Ws[r][wc] =
                *(const float4*)(Q + (size_t)(kt + r) * 256 + col0 + wc);
        }
        __syncthreads();
#pragma unroll
        for (int kk = 0; kk < 16; kk++) {
            float4 a0 = *(const float4*)&As[kk][ty * 4];
            float4 a1 = *(const float4*)&As[kk][64 + ty * 4];
            float4 w0 = *(const float4*)&Ws[kk][tx * 4];
            float4 w1 = *(const float4*)&Ws[kk][64 + tx * 4];
            float af[8] = {a0.x, a0.y, a0.z, a0.w, a1.x, a1.y, a1.z, a1.w};
            float wf[8] = {w0.x, w0.y, w0.z, w0.w, w1.x, w1.y, w1.z, w1.w};
#pragma unroll
            for (int i = 0; i < 8; i++)
#pragma unroll
                for (int j = 0; j < 8; j++)
                    acc[i][j] = fmaf(af[i], wf[j], acc[i][j]);
        }
        __syncthreads();
    }
#pragma unroll
    for (int ih = 0; ih < 2; ih++)
#pragma unroll
        for (int i = 0; i < 4; i++) {
            int r = row0 + ih * 64 + ty * 4 + i;
#pragma unroll
            for (int jh = 0; jh < 2; jh++)
#pragma unroll
                for (int j = 0; j < 4; j++)
                    C[(size_t)r * 256 + col0 + jh * 64 + tx * 4 + j] =
                        acc[ih * 4 + i][jh * 4 + j];
        }
}

// combined bias vectors: g_vbias[c] = b_c @ Q_c (+ rb1 for c==21), grid (22)
__global__ void __launch_bounds__(256) vbias_kernel(
    const float* __restrict__ mw1, const float* __restrict__ uw1,
    const float* __restrict__ rw1, const float* __restrict__ mb2,
    const float* __restrict__ ub2, const float* __restrict__ rb1)
{
    int c = blockIdx.x;
    const float* b = (c < 6) ? mb2 + (size_t)c * 256
                   : (c < 21) ? ub2 + (size_t)((c - 6) / 3) * 256
                              : ub2 + (size_t)5 * 256;
    const float* Q = combo_Q(c, mw1, uw1, rw1);
    int n = threadIdx.x;
    float s = 0.f;
    for (int k = 0; k < 256; k++) s = fmaf(b[k], Q[(size_t)k * 256 + n], s);
    if (c == 21) s += rb1[n];
    g_vbias[(size_t)c * 256 + n] = s;
}

// ---------------------------------------------------------------------------
// Weight transpose to fp16: pool[z][n][k] = fp16(S_z[k][n])
// ---------------------------------------------------------------------------
__global__ void wsplit_kernel(
    const float* __restrict__ mw1, const float* __restrict__ uw1,
    const float* __restrict__ rw2, __half* __restrict__ wt)
{
    int z = blockIdx.z;
    const float* W;
    int N = 256;
    if (z < 2)       W = mw1 + (size_t)z * 65536;
    else if (z == 2) W = uw1;
    else if (z < 25) W = g_wcomb + (size_t)(z - 3) * 65536;
    else { W = rw2; N = 128; }

    int k0 = blockIdx.x * 32, n0 = blockIdx.y * 32;
    if (n0 >= N) return;
    __shared__ float t[32][33];
    for (int i = threadIdx.y; i < 32; i += 8)
        t[i][threadIdx.x] = W[(size_t)(k0 + i) * N + n0 + threadIdx.x];
    __syncthreads();
    size_t base = (size_t)z * 65536;
    for (int i = threadIdx.y; i < 32; i += 8)
        wt[base + (size_t)(n0 + i) * 256 + k0 + threadIdx.x] =
            __float2half(t[threadIdx.x][i]);
}

// ---------------------------------------------------------------------------
// fp16 GEMM via mma.sync, 1-term (A already fp16), double-buffered cp.async.
// Tile (MI*32) x 128, 8 warps. MI=4: 2 CTAs/SM; MI=5: 1 CTA/SM.
// flags: 1=RELU 2=ADDC 4=BIAS 8=ROWB 16=HALF_OUT(bz0)
// ---------------------------------------------------------------------------
template <int MI>
__global__ void __launch_bounds__(256, (MI == 4) ? 2 : 1) tgemm(
    const __half* __restrict__ A,
    const __half* __restrict__ wt,
    int s0, int s1, int s2,
    const float* __restrict__ b0p, const float* __restrict__ b1p,
    const float* __restrict__ b2p,
    const float* __restrict__ rbias, const float* __restrict__ rowscale,
    const float* __restrict__ Cprev,
    float* C0, float* C1, float* C2,
    int M, int ldc, int flags)
{
    constexpr int TM = MI * 32;
    constexpr int WBASE = TM * 80;
    constexpr int BUFSZ = WBASE + 10240;

    extern __shared__ __align__(16) char smem[];

    int bz = blockIdx.z;
    int slot = (bz == 0) ? s0 : (bz == 1 ? s1 : s2);
    float* C = (bz == 0) ? C0 : (bz == 1 ? C1 : C2);
    const float* bias = (bz == 0) ? b0p : (bz == 1 ? b1p : b2p);
    const __half* Wp = wt + (size_t)slot * 65536;
    bool half_out = (flags & 16) && (bz == 0);

    uint32_t sb = smem_u32(smem);
    int tid = threadIdx.x;
    int lane = tid & 31, wid = tid >> 5;
    int wr = wid >> 2, wc = wid & 3;
    int row0 = blockIdx.y * TM, col0 = blockIdx.x * 128;

    float acc[MI][4][4];
#pragma unroll
    for (int i = 0; i < MI; i++)
#pragma unroll
        for (int j = 0; j < 4; j++)
#pragma unroll
            for (int k = 0; k < 4; k++) acc[i][j][k] = 0.f;

    int a_row = lane & 15;
    int a_kh = (lane >> 4) * 8;
    int bg = lane >> 3;
    int b_n = (lane & 7) + (bg >> 1) * 8;
    int b_kh = (bg & 1) * 8;

    int lrow = tid >> 1;
    int lhalf = tid & 1;
    size_t wgoff = (size_t)(col0 + lrow) * 256 + lhalf * 16;
    uint32_t wsoff = (uint32_t)(lrow * 80 + lhalf * 32);

#define ISSUE_AW(ch, buf)                                                   \
    do {                                                                    \
        uint32_t bb_ = sb + (buf) * BUFSZ;                                  \
        for (int idx = tid; idx < TM * 4; idx += 256) {                     \
            int r_ = idx >> 2, seg_ = idx & 3;                              \
            cp16(bb_ + (uint32_t)(r_ * 80 + seg_ * 16),                     \
                 A + (size_t)(row0 + r_) * 256 + (ch) * 32 + seg_ * 8);     \
        }                                                                   \
        const __half* pw_ = Wp + wgoff + (ch) * 32;                         \
        cp16(bb_ + WBASE + wsoff, pw_);                                     \
        cp16(bb_ + WBASE + wsoff + 16, pw_ + 8);                            \
    } while (0)

    ISSUE_AW(0, 0);
    cp_commit();
    cp_wait0();
    __syncthreads();

#pragma unroll 2
    for (int ch = 0; ch < 8; ch++) {
        int buf = ch & 1;
        if (ch < 7) {
            ISSUE_AW(ch + 1, buf ^ 1);
            cp_commit();
        }
        uint32_t base = sb + buf * BUFSZ;
#pragma unroll
        for (int ks = 0; ks < 2; ks++) {
            uint32_t Af[MI][4], Bf[2][4];
            uint32_t acol = (uint32_t)((ks * 16 + a_kh) * 2);
            uint32_t bcol = (uint32_t)((ks * 16 + b_kh) * 2);
#pragma unroll
            for (int nj = 0; nj < 2; nj++)
                ldm_x4(Bf[nj], base + WBASE +
                               (uint32_t)((wc * 32 + nj * 16 + b_n) * 80) + bcol);
#pragma unroll
            for (int mi = 0; mi < MI; mi++)
                ldm_x4(Af[mi], base +
                               (uint32_t)((wr * (MI * 16) + mi * 16 + a_row) * 80) + acol);
#pragma unroll
            for (int mi = 0; mi < MI; mi++)
#pragma unroll
                for (int ni = 0; ni < 4; ni++) {
                    int nj = ni >> 1, off = (ni & 1) * 2;
                    mma_f16(acc[mi][ni], Af[mi], Bf[nj][off], Bf[nj][off + 1]);
                }
        }
        if (ch < 7) {
            cp_wait0();
            __syncthreads();
        }
    }

    // ---- epilogue ----
#pragma unroll
    for (int mi = 0; mi < MI; mi++) {
        int m0 = row0 + wr * (MI * 16) + mi * 16 + (lane >> 2);
        int m1 = m0 + 8;
        float rs0 = 0.f, rs1 = 0.f;
        if (flags & 8) {
            if (m0 < M) rs0 = rowscale[m0];
            if (m1 < M) rs1 = rowscale[m1];
        }
#pragma unroll
        for (int ni = 0; ni < 4; ni++) {
            int nc = col0 + wc * 32 + ni * 8 + (lane & 3) * 2;
            float b0 = 0.f, b1 = 0.f, r0b = 0.f, r1b = 0.f;
            if (flags & 4) { b0 = bias[nc]; b1 = bias[nc + 1]; }
            if (flags & 8) { r0b = rbias[nc]; r1b = rbias[nc + 1]; }
            float* a = acc[mi][ni];
            if (m0 < M) {
                float v0 = a[0] + b0, v1 = a[1] + b1;
                if (flags & 8) { v0 = fmaf(rs0, r0b, v0); v1 = fmaf(rs0, r1b, v1); }
                if (flags & 2) {
                    v0 += Cprev[(size_t)m0 * 256 + nc];
                    v1 += Cprev[(size_t)m0 * 256 + nc + 1];
                }
                if (flags & 1) { v0 = fmaxf(v0, 0.f); v1 = fmaxf(v1, 0.f); }
                if (half_out)
                    *(__half2*)((__half*)C + (size_t)m0 * ldc + nc) =
                        __floats2half2_rn(v0, v1);
                else
                    *(float2*)(C + (size_t)m0 * ldc + nc) = make_float2(v0, v1);
            }
            if (m1 < M) {
                float v0 = a[2] + b0, v1 = a[3] + b1;
                if (flags & 8) { v0 = fmaf(rs1, r0b, v0); v1 = fmaf(rs1, r1b, v1); }
                if (flags & 2) {
                    v0 += Cprev[(size_t)m1 * 256 + nc];
                    v1 += Cprev[(size_t)m1 * 256 + nc + 1];
                }
                if (flags & 1) { v0 = fmaxf(v0, 0.f); v1 = fmaxf(v1, 0.f); }
                if (half_out)
                    *(__half2*)((__half*)C + (size_t)m1 * ldc + nc) =
                        __floats2half2_rn(v0, v1);
                else
                    *(float2*)(C + (size_t)m1 * ldc + nc) = make_float2(v0, v1);
            }
        }
    }
#undef ISSUE_AW
}

// ---------------------------------------------------------------------------
// Embed: x0 = fp16(atom @ embed_w + embed_b)
// ---------------------------------------------------------------------------
#define EMB_NODES 16
__global__ void __launch_bounds__(256) embed_kernel(
    const float* __restrict__ atom, const float* __restrict__ w,
    const float* __restrict__ b, __half* __restrict__ x16)
{
    __shared__ float s_af[EMB_NODES][NATOM];
    int n0 = blockIdx.x * EMB_NODES;
    int tid = threadIdx.x;
    for (int i = tid; i < EMB_NODES * NATOM; i += 256) {
        int r = i / NATOM, c = i % NATOM;
        int n = n0 + r;
        s_af[r][c] = (n < N_NODES) ? atom[(size_t)n * NATOM + c] : 0.f;
    }
    __syncthreads();
    int j = tid;
    float acc[EMB_NODES];
    float bj = b[j];
#pragma unroll
    for (int r = 0; r < EMB_NODES; r++) acc[r] = bj;
    for (int k = 0; k < NATOM; k++) {
        float wv = w[k * HID + j];
#pragma unroll
        for (int r = 0; r < EMB_NODES; r++) acc[r] = fmaf(s_af[r][k], wv, acc[r]);
    }
#pragma unroll
    for (int r = 0; r < EMB_NODES; r++) {
        int n = n0 + r;
        if (n < N_NODES) x16[(size_t)n * HID + j] = __float2half(acc[r]);
    }
}

// ---------------------------------------------------------------------------
// CSR build
// ---------------------------------------------------------------------------
__global__ void count_kernel(const int* __restrict__ dst)
{
    int e = blockIdx.x * blockDim.x + threadIdx.x;
    if (e < N_EDGES) atomicAdd(&g_deg[dst[e]], 1);
}

__global__ void __launch_bounds__(1024) scan_kernel()
{
    __shared__ int sdeg[10240];
    __shared__ int warpsum[32];
    int tid = threadIdx.x;
#pragma unroll
    for (int i = 0; i < 10; i++) {
        int idx = i * 1024 + tid;
        sdeg[idx] = (idx < N_NODES) ? g_deg[idx] : 0;
    }
    __syncthreads();
    int base = tid * 10;
    int v[10];
    int tot = 0;
#pragma unroll
    for (int i = 0; i < 10; i++) {
        v[i] = sdeg[base + i];
        tot += v[i];
    }
    int lane = tid & 31, wid = tid >> 5;
    int x = tot;
#pragma unroll
    for (int off = 1; off < 32; off <<= 1) {
        int y = __shfl_up_sync(~0u, x, off);
        if (lane >= off) x += y;
    }
    if (lane == 31) warpsum[wid] = x;
    __syncthreads();
    if (wid == 0) {
        int w = warpsum[lane];
#pragma unroll
        for (int off = 1; off < 32; off <<= 1) {
            int y = __shfl_up_sync(~0u, w, off);
            if (lane >= off) w += y;
        }
        warpsum[lane] = w;
    }
    __syncthreads();
    int run = x - tot + (wid ? warpsum[wid - 1] : 0);
    if (tid == 0) g_rowptr[0] = 0;
#pragma unroll
    for (int i = 0; i < 10; i++) {
        int idx = base + i;
        if (idx < N_NODES) {
            g_cursor[idx] = run;
            run += v[i];
            g_rowptr[idx + 1] = run;
            g_degf[idx] = (float)v[i];
        }
    }
}

__global__ void fill_kernel(const int* __restrict__ src,
                            const int* __restrict__ dst,
                            const float* __restrict__ ef)
{
    int e = blockIdx.x * blockDim.x + threadIdx.x;
    if (e >= N_EDGES) return;
    int d = dst[e];
    int pos = atomicAdd(&g_cursor[d], 1);
    g_ssrc[pos] = src[e];
#pragma unroll
    for (int q = 0; q < NBOND; q++)
        g_sef[(size_t)pos * NBOND + q] = ef[(size_t)e * NBOND + q];
}

// ---------------------------------------------------------------------------
// Aggregate: ragg16[n] = fp16( sum_in-edges relu(xa16[src]+xb[n]+ef@W1c+b1) )
// ---------------------------------------------------------------------------
#define NPC 8
#define CHE 32
__global__ void __launch_bounds__(256) aggregate_kernel(
    const __half* __restrict__ xa16, const float* __restrict__ xb,
    const float* __restrict__ w1c, const float* __restrict__ b1,
    __half* __restrict__ ragg16)
{
    __shared__ int   s_src[CHE];
    __shared__ float s_ef[CHE][NBOND];

    int n0 = blockIdx.x * NPC;
    int c = threadIdx.x;

    float wreg[NBOND];
#pragma unroll
    for (int q = 0; q < NBOND; q++) wreg[q] = w1c[q * 256 + c];
    float b1c = b1[c];

    for (int ni = 0; ni < NPC; ni++) {
        int n = n0 + ni;
        if (n >= N_NODES) break;
        float base_v = b1c + xb[(size_t)n * HID + c];
        int beg = g_rowptr[n], end = g_rowptr[n + 1];
        float acc = 0.f;
        for (int b0 = beg; b0 < end; b0 += CHE) {
            int m = min(CHE, end - b0);
            __syncthreads();
            if (c < m) s_src[c] = g_ssrc[b0 + c];
            if (c < m * NBOND)
                s_ef[c / NBOND][c % NBOND] = g_sef[(size_t)b0 * NBOND + c];
            __syncthreads();
            for (int j = 0; j < m; j++) {
                float t = base_v +
                          __half2float(xa16[(size_t)s_src[j] * HID + c]);
#pragma unroll
                for (int q = 0; q < NBOND; q++)
                    t = fmaf(s_ef[j][q], wreg[q], t);
                acc += fmaxf(t, 0.f);
            }
        }
        ragg16[(size_t)n * HID + c] = __float2half(acc);
    }
}

// ---------------------------------------------------------------------------
// Readout final: out = mean_n( r2[n,:] . w3 + b3 )
// ---------------------------------------------------------------------------
__global__ void __launch_bounds__(256) readout_final(
    const float* __restrict__ r2, const float* __restrict__ w3,
    const float* __restrict__ b3, float* __restrict__ out)
{
    __shared__ float sred[256];
    int n = blockIdx.x * 256 + threadIdx.x;
    float v = 0.f;
    if (n < N_NODES) {
        const float* row = r2 + (size_t)n * 128;
        float s = 0.f;
#pragma unroll
        for (int k = 0; k < 128; k += 4) {
            float4 rv = *(const float4*)(row + k);
            float4 wv = *(const float4*)(w3 + k);
            s += rv.x * wv.x + rv.y * wv.y + rv.z * wv.z + rv.w * wv.w;
        }
        v = (s + b3[0]) * (1.0f / N_NODES);
    }
    sred[threadIdx.x] = v;
    __syncthreads();
    for (int st = 128; st > 0; st >>= 1) {
        if (threadIdx.x < st) sred[threadIdx.x] += sred[threadIdx.x + st];
        __syncthreads();
    }
    if (threadIdx.x == 0) atomicAdd(out, sred[0]);
}

// ---------------------------------------------------------------------------
// Launch
// ---------------------------------------------------------------------------
extern "C" void kernel_launch(void* const* d_in, const int* in_sizes, int n_in,
                              void* d_out, int out_size)
{
    const float* atom = (const float*)d_in[0];
    const int*   eidx = (const int*)d_in[1];
    const float* ef   = (const float*)d_in[2];
    const float* embw = (const float*)d_in[3];
    const float* embb = (const float*)d_in[4];
    const float* mw1  = (const float*)d_in[5];
    const float* mb1  = (const float*)d_in[6];
    const float* mw2  = (const float*)d_in[7];
    const float* mb2  = (const float*)d_in[8];
    const float* uw1  = (const float*)d_in[9];
    const float* ub1  = (const float*)d_in[10];
    const float* uw2  = (const float*)d_in[11];
    const float* ub2  = (const float*)d_in[12];
    const float* rw1  = (const float*)d_in[13];
    const float* rb1  = (const float*)d_in[14];
    const float* rw2  = (const float*)d_in[15];
    const float* rb2  = (const float*)d_in[16];
    const float* rw3  = (const float*)d_in[17];
    const float* rb3  = (const float*)d_in[18];

    const int* src = eidx;
    const int* dst = eidx + N_EDGES;

    float *px, *pxa, *pxb, *pagg, *pt1, *ph, *pdegf, *pvb;
    int* pdeg;
    __half* pwt;
    cudaGetSymbolAddress((void**)&px,    g_x);
    cudaGetSymbolAddress((void**)&pxa,   g_xa);
    cudaGetSymbolAddress((void**)&pxb,   g_xb);
    cudaGetSymbolAddress((void**)&pagg,  g_agg);
    cudaGetSymbolAddress((void**)&pt1,   g_t1);
    cudaGetSymbolAddress((void**)&ph,    g_h);
    cudaGetSymbolAddress((void**)&pdeg,  g_deg);
    cudaGetSymbolAddress((void**)&pdegf, g_degf);
    cudaGetSymbolAddress((void**)&pvb,   g_vbias);
    cudaGetSymbolAddress((void**)&pwt,   g_wt);

    const int SM4 = 2 * (4 * 32 * 80 + 10240);   // 40960
    const int SM5 = 2 * (5 * 32 * 80 + 10240);   // 46080
    static bool attr_done = false;
    if (!attr_done) {
        cudaFuncSetAttribute(tgemm<4>,
                             cudaFuncAttributeMaxDynamicSharedMemorySize, SM4);
        cudaFuncSetAttribute(tgemm<5>,
                             cudaFuncAttributeMaxDynamicSharedMemorySize, SM5);
        attr_done = true;
    }

    static bool inited = false;
    static cudaStream_t sA, sB;
    static cudaEvent_t evRoot, evA, evB;
    if (!inited) {
        cudaStreamCreateWithFlags(&sA, cudaStreamNonBlocking);
        cudaStreamCreateWithFlags(&sB, cudaStreamNonBlocking);
        cudaEventCreateWithFlags(&evRoot, cudaEventDisableTiming);
        cudaEventCreateWithFlags(&evA, cudaEventDisableTiming);
        cudaEventCreateWithFlags(&evB, cudaEventDisableTiming);
        inited = true;
    }

    // d_out zero issued first (off the tail)
    cudaMemsetAsync(d_out, 0, sizeof(float));

    // fork
    cudaEventRecord(evRoot, 0);
    cudaStreamWaitEvent(sA, evRoot, 0);
    cudaStreamWaitEvent(sB, evRoot, 0);

    // stream A: weight critical path (combine -> wsplit)
    combine_kernel<<<dim3(2, 2, NCOMB), 256, 0, sA>>>(mw1, uw1, mw2, uw2, rw1);
    wsplit_kernel<<<dim3(8, 8, NSLOTS), dim3(32, 8), 0, sA>>>(mw1, uw1, rw2, pwt);
    cudaEventRecord(evA, sA);

    // stream B: CSR pipeline + vbias (off the weight critical path)
    cudaMemsetAsync(pdeg, 0, sizeof(int) * N_NODES, sB);
    count_kernel<<<(N_EDGES + 255) / 256, 256, 0, sB>>>(dst);
    scan_kernel<<<1, 1024, 0, sB>>>();
    fill_kernel<<<(N_EDGES + 255) / 256, 256, 0, sB>>>(src, dst, ef);
    vbias_kernel<<<NCOMB, 256, 0, sB>>>(mw1, uw1, rw1, mb2, ub2, rb1);
    cudaEventRecord(evB, sB);

    // main stream: embed (overlaps setup), then join weight pipeline
    embed_kernel<<<(N_NODES + EMB_NODES - 1) / EMB_NODES, 256>>>(
        atom, embw, embb, (__half*)px);
    cudaStreamWaitEvent(0, evA, 0);

    const int MT5 = (N_NODES + 159) / 160;     // 63
    dim3 gG3(2, (N_NODES + 127) / 128, 3);     // tgemm<4>, 474 CTAs
    dim3 gS(2, MT5, 1);                        // tgemm<5>, 126 CTAs
    const int AGG_BLK = (N_NODES + NPC - 1) / NPC;  // 1250

    // layer 0 inputs: xa(fp16),xb,t1 from x0(fp16)  (t1 has no bias at l=0)
    tgemm<4><<<gG3, 256, SM4>>>((const __half*)px, pwt, 0, 1, 2,
                                nullptr, nullptr, nullptr,
                                nullptr, nullptr, nullptr,
                                pxa, pxb, pt1, N_NODES, 256, 16);

    // join CSR + vbias pipeline before first aggregate
    cudaStreamWaitEvent(0, evB, 0);

    for (int l = 0; l < NLAYERS; l++) {
        const float* W1c = mw1 + (size_t)l * 518 * HID + 512 * HID;

        // ragg16[n] = fp16( sum relu(xa16[src]+xb[n]+ef@W1c+b1) )
        aggregate_kernel<<<AGG_BLK, 256>>>((const __half*)pxa, pxb, W1c,
                                           mb1 + (size_t)l * HID,
                                           (__half*)pagg);

        // h(fp16) = relu(ragg@(W2@U1b) + deg*(b2@U1b) + ub1 + t1)
        tgemm<5><<<gS, 256, SM5>>>((const __half*)pagg, pwt, 3 + l, 0, 0,
                                   ub1 + (size_t)l * HID, nullptr, nullptr,
                                   pvb + (size_t)l * 256, pdegf, pt1,
                                   ph, nullptr, nullptr, N_NODES, 256,
                                   1 | 2 | 4 | 8 | 16);

        if (l < NLAYERS - 1) {
            // next xa(fp16),xb,t1 directly from h(fp16) with combined weights
            int cb = 6 + 3 * l;
            tgemm<4><<<gG3, 256, SM4>>>((const __half*)ph, pwt,
                                        9 + 3 * l, 10 + 3 * l, 11 + 3 * l,
                                        pvb + (size_t)cb * 256,
                                        pvb + (size_t)(cb + 1) * 256,
                                        pvb + (size_t)(cb + 2) * 256,
                                        nullptr, nullptr, nullptr,
                                        pxa, pxb, pt1, N_NODES, 256, 4 | 16);
        }
    }

    // readout r1(fp16) = relu(h@(U2_5@rw1) + (ub2_5@rw1 + rb1))
    tgemm<5><<<gS, 256, SM5>>>((const __half*)ph, pwt, 24, 0, 0,
                               pvb + (size_t)21 * 256, nullptr, nullptr,
                               nullptr, nullptr, nullptr,
                               pt1, nullptr, nullptr, N_NODES, 256, 1 | 4 | 16);
    // r2(fp32) = relu(r1@rw2 + rb2)
    dim3 gR(1, MT5, 1);
    tgemm<5><<<gR, 256, SM5>>>((const __half*)pt1, pwt, 25, 0, 0,
                               rb2, nullptr, nullptr,
                               nullptr, nullptr, nullptr,
                               pxb, nullptr, nullptr, N_NODES, 128, 1 | 4);

    readout_final<<<(N_NODES + 255) / 256, 256>>>(pxb, rw3, rb3, (float*)d_out);
}

// round 16
// speedup vs baseline: 1.5277x; 1.1969x over previous
#include <cuda_runtime.h>
#include <cuda_fp16.h>
#include <cstdint>

#define N_NODES 10000
#define N_EDGES 160000
#define HID 256
#define NBOND 6
#define NATOM 62
#define NLAYERS 6
#define NSLOTS 26
#define NCOMB 22

// ---------------- scratch (device globals; no allocation allowed) ----------
__device__ float g_x[N_NODES * HID];    // x0 as __half
__device__ float g_xa[N_NODES * HID];   // xa as __half
__device__ float g_xb[N_NODES * HID];   // xb as __half
__device__ float g_agg[N_NODES * HID];  // ragg as __half
__device__ float g_t1[N_NODES * HID];   // t1 fp32 / r1 as __half
__device__ float g_h[N_NODES * HID];    // h as __half

__device__ int   g_deg[N_NODES];
__device__ int   g_rowptr[N_NODES + 1];
__device__ int   g_cursor[N_NODES];
__device__ int   g_ssrc[N_EDGES];
__device__ float g_sef[N_EDGES * NBOND];
__device__ float g_degf[N_NODES];

__device__ float g_wcomb[NCOMB * 65536];
__device__ float g_vbias[NCOMB * 256];
__device__ __half g_wt[NSLOTS * 256 * 256];

// ---------------- helpers ---------------------------------------------------
__device__ __forceinline__ uint32_t smem_u32(const void* p) {
    uint32_t a;
    asm("{ .reg .u64 t; cvta.to.shared.u64 t, %1; cvt.u32.u64 %0, t; }"
        : "=r"(a) : "l"(p));
    return a;
}
__device__ __forceinline__ void ldm_x4(uint32_t* r, uint32_t addr) {
    asm volatile("ldmatrix.sync.aligned.m8n8.x4.shared.b16 {%0,%1,%2,%3}, [%4];"
                 : "=r"(r[0]), "=r"(r[1]), "=r"(r[2]), "=r"(r[3]) : "r"(addr));
}
__device__ __forceinline__ void mma_f16(float* c, const uint32_t* a,
                                        uint32_t b0, uint32_t b1) {
    asm volatile(
        "mma.sync.aligned.m16n8k16.row.col.f32.f16.f16.f32 "
        "{%0,%1,%2,%3}, {%4,%5,%6,%7}, {%8,%9}, {%0,%1,%2,%3};"
        : "+f"(c[0]), "+f"(c[1]), "+f"(c[2]), "+f"(c[3])
        : "r"(a[0]), "r"(a[1]), "r"(a[2]), "r"(a[3]), "r"(b0), "r"(b1));
}
__device__ __forceinline__ void cp16(uint32_t dst, const void* src) {
    asm volatile("cp.async.cg.shared.global [%0], [%1], 16;"
                 :: "r"(dst), "l"(src));
}
__device__ __forceinline__ void cp_commit() {
    asm volatile("cp.async.commit_group;" ::: "memory");
}
__device__ __forceinline__ void cp_wait0() {
    asm volatile("cp.async.wait_group 0;" ::: "memory");
}

// ---------------------------------------------------------------------------
// Combo source pointers:
//  c in [0,6):   P = W2_l (mw2),  Q = U1b_l          (WU_l = W2@U1b)
//  c in [6,21):  P = U2_m (uw2),  Q in {W1a,W1b,U1a} of layer m+1
//  c == 21:      P = U2_5,        Q = rw1
// ---------------------------------------------------------------------------
__device__ __forceinline__ const float* combo_Q(
    int c, const float* mw1, const float* uw1, const float* rw1)
{
    if (c < 6) return uw1 + (size_t)c * 131072 + 65536;
    if (c < 21) {
        int m = (c - 6) / 3, t = (c - 6) % 3;
        int l = m + 1;
        if (t == 0) return mw1 + (size_t)l * 518 * 256;
        if (t == 1) return mw1 + (size_t)l * 518 * 256 + 65536;
        return uw1 + (size_t)l * 131072;
    }
    return rw1;
}

// fp32 setup GEMM: g_wcomb[c] = P_c @ Q_c   (256x256x256), grid (2,2,22)
__global__ void __launch_bounds__(256) combine_kernel(
    const float* __restrict__ mw1, const float* __restrict__ uw1,
    const float* __restrict__ mw2, const float* __restrict__ uw2,
    const float* __restrict__ rw1)
{
    int c = blockIdx.z;
    const float* P = (c < 6) ? mw2 + (size_t)c * 65536
                   : (c < 21) ? uw2 + (size_t)((c - 6) / 3) * 65536
                              : uw2 + (size_t)5 * 65536;
    const float* Q = combo_Q(c, mw1, uw1, rw1);
    float* C = g_wcomb + (size_t)c * 65536;

    __shared__ float As[16][128];
    __shared__ float Ws[16][128];
    int col0 = blockIdx.x * 128, row0 = blockIdx.y * 128;
    int tid = threadIdx.x;
    int tx = tid & 15, ty = tid >> 4;

    float acc[8][8];
#pragma unroll
    for (int i = 0; i < 8; i++)
#pragma unroll
        for (int j = 0; j < 8; j++) acc[i][j] = 0.f;

    int ar = tid >> 2, ac = (tid & 3) << 2;
    int wr = tid >> 5, wc = (tid & 31) << 2;

    for (int kt = 0; kt < 256; kt += 16) {
#pragma unroll
        for (int i = 0; i < 2; i++) {
            int r = ar + i * 64;
            float4 v = *(const float4*)(P + (size_t)(row0 + r) * 256 + kt + ac);
            As[ac + 0][r] = v.x; As[ac + 1][r] = v.y;
            As[ac + 2][r] = v.z; As[ac + 3][r] = v.w;
        }
#pragma unroll
        for (int i = 0; i < 2; i++) {
            int r = wr + i * 8;
            *(float4*)&Ws[r][wc] =
                *(const float4*)(Q + (size_t)(kt + r) * 256 + col0 + wc);
        }
        __syncthreads();
#pragma unroll
        for (int kk = 0; kk < 16; kk++) {
            float4 a0 = *(const float4*)&As[kk][ty * 4];
            float4 a1 = *(const float4*)&As[kk][64 + ty * 4];
            float4 w0 = *(const float4*)&Ws[kk][tx * 4];
            float4 w1 = *(const float4*)&Ws[kk][64 + tx * 4];
            float af[8] = {a0.x, a0.y, a0.z, a0.w, a1.x, a1.y, a1.z, a1.w};
            float wf[8] = {w0.x, w0.y, w0.z, w0.w, w1.x, w1.y, w1.z, w1.w};
#pragma unroll
            for (int i = 0; i < 8; i++)
#pragma unroll
                for (int j = 0; j < 8; j++)
                    acc[i][j] = fmaf(af[i], wf[j], acc[i][j]);
        }
        __syncthreads();
    }
#pragma unroll
    for (int ih = 0; ih < 2; ih++)
#pragma unroll
        for (int i = 0; i < 4; i++) {
            int r = row0 + ih * 64 + ty * 4 + i;
#pragma unroll
            for (int jh = 0; jh < 2; jh++)
#pragma unroll
                for (int j = 0; j < 4; j++)
                    C[(size_t)r * 256 + col0 + jh * 64 + tx * 4 + j] =
                        acc[ih * 4 + i][jh * 4 + j];
        }
}

// combined bias vectors: g_vbias[c] = b_c @ Q_c (+ rb1 for c==21), grid (22)
__global__ void __launch_bounds__(256) vbias_kernel(
    const float* __restrict__ mw1, const float* __restrict__ uw1,
    const float* __restrict__ rw1, const float* __restrict__ mb2,
    const float* __restrict__ ub2, const float* __restrict__ rb1)
{
    int c = blockIdx.x;
    const float* b = (c < 6) ? mb2 + (size_t)c * 256
                   : (c < 21) ? ub2 + (size_t)((c - 6) / 3) * 256
                              : ub2 + (size_t)5 * 256;
    const float* Q = combo_Q(c, mw1, uw1, rw1);
    int n = threadIdx.x;
    float s = 0.f;
    for (int k = 0; k < 256; k++) s = fmaf(b[k], Q[(size_t)k * 256 + n], s);
    if (c == 21) s += rb1[n];
    g_vbias[(size_t)c * 256 + n] = s;
}

// ---------------------------------------------------------------------------
// Weight transpose to fp16: pool[z][n][k] = fp16(S_z[k][n])
// ---------------------------------------------------------------------------
__global__ void wsplit_kernel(
    const float* __restrict__ mw1, const float* __restrict__ uw1,
    const float* __restrict__ rw2, __half* __restrict__ wt)
{
    int z = blockIdx.z;
    const float* W;
    int N = 256;
    if (z < 2)       W = mw1 + (size_t)z * 65536;
    else if (z == 2) W = uw1;
    else if (z < 25) W = g_wcomb + (size_t)(z - 3) * 65536;
    else { W = rw2; N = 128; }

    int k0 = blockIdx.x * 32, n0 = blockIdx.y * 32;
    if (n0 >= N) return;
    __shared__ float t[32][33];
    for (int i = threadIdx.y; i < 32; i += 8)
        t[i][threadIdx.x] = W[(size_t)(k0 + i) * N + n0 + threadIdx.x];
    __syncthreads();
    size_t base = (size_t)z * 65536;
    for (int i = threadIdx.y; i < 32; i += 8)
        wt[base + (size_t)(n0 + i) * 256 + k0 + threadIdx.x] =
            __float2half(t[threadIdx.x][i]);
}

// ---------------------------------------------------------------------------
// fp16 GEMM via mma.sync, 1-term (A already fp16), double-buffered cp.async.
// Tile (MI*32) x 128, 8 warps. MI=4: 2 CTAs/SM; MI=5: 1 CTA/SM.
// flags: 1=RELU 2=ADDC 4=BIAS 8=ROWB(rowscale*rbias)
//        16=HALF_OUT(bz0) 32=HALF_OUT(bz1)
//        64=DOT_OUT(bz0): no store; out += sum(v*rbias)/N (+b2p[0] once)
// ---------------------------------------------------------------------------
template <int MI>
__global__ void __launch_bounds__(256, (MI == 4) ? 2 : 1) tgemm(
    const __half* __restrict__ A,
    const __half* __restrict__ wt,
    int s0, int s1, int s2,
    const float* __restrict__ b0p, const float* __restrict__ b1p,
    const float* __restrict__ b2p,
    const float* __restrict__ rbias, const float* __restrict__ rowscale,
    const float* __restrict__ Cprev,
    float* C0, float* C1, float* C2,
    int M, int ldc, int flags)
{
    constexpr int TM = MI * 32;
    constexpr int WBASE = TM * 80;
    constexpr int BUFSZ = WBASE + 10240;

    extern __shared__ __align__(16) char smem[];

    int bz = blockIdx.z;
    int slot = (bz == 0) ? s0 : (bz == 1 ? s1 : s2);
    float* C = (bz == 0) ? C0 : (bz == 1 ? C1 : C2);
    const float* bias = (bz == 0) ? b0p : (bz == 1 ? b1p : b2p);
    const __half* Wp = wt + (size_t)slot * 65536;
    bool half_out = ((flags & 16) && bz == 0) || ((flags & 32) && bz == 1);
    bool dot_out = (flags & 64) && (bz == 0);

    uint32_t sb = smem_u32(smem);
    int tid = threadIdx.x;
    int lane = tid & 31, wid = tid >> 5;
    int wr = wid >> 2, wc = wid & 3;
    int row0 = blockIdx.y * TM, col0 = blockIdx.x * 128;

    float acc[MI][4][4];
#pragma unroll
    for (int i = 0; i < MI; i++)
#pragma unroll
        for (int j = 0; j < 4; j++)
#pragma unroll
            for (int k = 0; k < 4; k++) acc[i][j][k] = 0.f;

    int a_row = lane & 15;
    int a_kh = (lane >> 4) * 8;
    int bg = lane >> 3;
    int b_n = (lane & 7) + (bg >> 1) * 8;
    int b_kh = (bg & 1) * 8;

    int lrow = tid >> 1;
    int lhalf = tid & 1;
    size_t wgoff = (size_t)(col0 + lrow) * 256 + lhalf * 16;
    uint32_t wsoff = (uint32_t)(lrow * 80 + lhalf * 32);

#define ISSUE_AW(ch, buf)                                                   \
    do {                                                                    \
        uint32_t bb_ = sb + (buf) * BUFSZ;                                  \
        for (int idx = tid; idx < TM * 4; idx += 256) {                     \
            int r_ = idx >> 2, seg_ = idx & 3;                              \
            cp16(bb_ + (uint32_t)(r_ * 80 + seg_ * 16),                     \
                 A + (size_t)(row0 + r_) * 256 + (ch) * 32 + seg_ * 8);     \
        }                                                                   \
        const __half* pw_ = Wp + wgoff + (ch) * 32;                         \
        cp16(bb_ + WBASE + wsoff, pw_);                                     \
        cp16(bb_ + WBASE + wsoff + 16, pw_ + 8);                            \
    } while (0)

    ISSUE_AW(0, 0);
    cp_commit();
    cp_wait0();
    __syncthreads();

#pragma unroll 2
    for (int ch = 0; ch < 8; ch++) {
        int buf = ch & 1;
        if (ch < 7) {
            ISSUE_AW(ch + 1, buf ^ 1);
            cp_commit();
        }
        uint32_t base = sb + buf * BUFSZ;
#pragma unroll
        for (int ks = 0; ks < 2; ks++) {
            uint32_t Af[MI][4], Bf[2][4];
            uint32_t acol = (uint32_t)((ks * 16 + a_kh) * 2);
            uint32_t bcol = (uint32_t)((ks * 16 + b_kh) * 2);
#pragma unroll
            for (int nj = 0; nj < 2; nj++)
                ldm_x4(Bf[nj], base + WBASE +
                               (uint32_t)((wc * 32 + nj * 16 + b_n) * 80) + bcol);
#pragma unroll
            for (int mi = 0; mi < MI; mi++)
                ldm_x4(Af[mi], base +
                               (uint32_t)((wr * (MI * 16) + mi * 16 + a_row) * 80) + acol);
#pragma unroll
            for (int mi = 0; mi < MI; mi++)
#pragma unroll
                for (int ni = 0; ni < 4; ni++) {
                    int nj = ni >> 1, off = (ni & 1) * 2;
                    mma_f16(acc[mi][ni], Af[mi], Bf[nj][off], Bf[nj][off + 1]);
                }
        }
        if (ch < 7) {
            cp_wait0();
            __syncthreads();
        }
    }

    // ---- epilogue ----
    float dot = 0.f;
#pragma unroll
    for (int mi = 0; mi < MI; mi++) {
        int m0 = row0 + wr * (MI * 16) + mi * 16 + (lane >> 2);
        int m1 = m0 + 8;
        float rs0 = 0.f, rs1 = 0.f;
        if (flags & 8) {
            if (m0 < M) rs0 = rowscale[m0];
            if (m1 < M) rs1 = rowscale[m1];
        }
#pragma unroll
        for (int ni = 0; ni < 4; ni++) {
            int nc = col0 + wc * 32 + ni * 8 + (lane & 3) * 2;
            float b0 = 0.f, b1 = 0.f, r0b = 0.f, r1b = 0.f;
            if (flags & 4) { b0 = bias[nc]; b1 = bias[nc + 1]; }
            if (flags & 8) { r0b = rbias[nc]; r1b = rbias[nc + 1]; }
            float* a = acc[mi][ni];
            if (m0 < M) {
                float v0 = a[0] + b0, v1 = a[1] + b1;
                if (flags & 8) { v0 = fmaf(rs0, r0b, v0); v1 = fmaf(rs0, r1b, v1); }
                if (flags & 2) {
                    v0 += Cprev[(size_t)m0 * 256 + nc];
                    v1 += Cprev[(size_t)m0 * 256 + nc + 1];
                }
                if (flags & 1) { v0 = fmaxf(v0, 0.f); v1 = fmaxf(v1, 0.f); }
                if (dot_out) {
                    dot += v0 * rbias[nc] + v1 * rbias[nc + 1];
                } else if (half_out)
                    *(__half2*)((__half*)C + (size_t)m0 * ldc + nc) =
                        __floats2half2_rn(v0, v1);
                else
                    *(float2*)(C + (size_t)m0 * ldc + nc) = make_float2(v0, v1);
            }
            if (m1 < M) {
                float v0 = a[2] + b0, v1 = a[3] + b1;
                if (flags & 8) { v0 = fmaf(rs1, r0b, v0); v1 = fmaf(rs1, r1b, v1); }
                if (flags & 2) {
                    v0 += Cprev[(size_t)m1 * 256 + nc];
                    v1 += Cprev[(size_t)m1 * 256 + nc + 1];
                }
                if (flags & 1) { v0 = fmaxf(v0, 0.f); v1 = fmaxf(v1, 0.f); }
                if (dot_out) {
                    dot += v0 * rbias[nc] + v1 * rbias[nc + 1];
                } else if (half_out)
                    *(__half2*)((__half*)C + (size_t)m1 * ldc + nc) =
                        __floats2half2_rn(v0, v1);
                else
                    *(float2*)(C + (size_t)m1 * ldc + nc) = make_float2(v0, v1);
            }
        }
    }
    if (dot_out) {
        float* sred = (float*)smem;
        __syncthreads();
        sred[tid] = dot;
        __syncthreads();
        for (int st = 128; st > 0; st >>= 1) {
            if (tid < st) sred[tid] += sred[tid + st];
            __syncthreads();
        }
        if (tid == 0) {
            float tot = sred[0] * (1.0f / N_NODES);
            if (blockIdx.y == 0) tot += b2p[0];
            atomicAdd(C, tot);
        }
    }
#undef ISSUE_AW
}

// ---------------------------------------------------------------------------
// Embed: x0 = fp16(atom @ embed_w + embed_b)
// ---------------------------------------------------------------------------
#define EMB_NODES 16
__global__ void __launch_bounds__(256) embed_kernel(
    const float* __restrict__ atom, const float* __restrict__ w,
    const float* __restrict__ b, __half* __restrict__ x16)
{
    __shared__ float s_af[EMB_NODES][NATOM];
    int n0 = blockIdx.x * EMB_NODES;
    int tid = threadIdx.x;
    for (int i = tid; i < EMB_NODES * NATOM; i += 256) {
        int r = i / NATOM, c = i % NATOM;
        int n = n0 + r;
        s_af[r][c] = (n < N_NODES) ? atom[(size_t)n * NATOM + c] : 0.f;
    }
    __syncthreads();
    int j = tid;
    float acc[EMB_NODES];
    float bj = b[j];
#pragma unroll
    for (int r = 0; r < EMB_NODES; r++) acc[r] = bj;
    for (int k = 0; k < NATOM; k++) {
        float wv = w[k * HID + j];
#pragma unroll
        for (int r = 0; r < EMB_NODES; r++) acc[r] = fmaf(s_af[r][k], wv, acc[r]);
    }
#pragma unroll
    for (int r = 0; r < EMB_NODES; r++) {
        int n = n0 + r;
        if (n < N_NODES) x16[(size_t)n * HID + j] = __float2half(acc[r]);
    }
}

// ---------------------------------------------------------------------------
// CSR build
// ---------------------------------------------------------------------------
__global__ void count_kernel(const int* __restrict__ dst)
{
    int e = blockIdx.x * blockDim.x + threadIdx.x;
    if (e < N_EDGES) atomicAdd(&g_deg[dst[e]], 1);
}

__global__ void __launch_bounds__(1024) scan_kernel()
{
    __shared__ int sdeg[10240];
    __shared__ int warpsum[32];
    int tid = threadIdx.x;
#pragma unroll
    for (int i = 0; i < 10; i++) {
        int idx = i * 1024 + tid;
        sdeg[idx] = (idx < N_NODES) ? g_deg[idx] : 0;
    }
    __syncthreads();
    int base = tid * 10;
    int v[10];
    int tot = 0;
#pragma unroll
    for (int i = 0; i < 10; i++) {
        v[i] = sdeg[base + i];
        tot += v[i];
    }
    int lane = tid & 31, wid = tid >> 5;
    int x = tot;
#pragma unroll
    for (int off = 1; off < 32; off <<= 1) {
        int y = __shfl_up_sync(~0u, x, off);
        if (lane >= off) x += y;
    }
    if (lane == 31) warpsum[wid] = x;
    __syncthreads();
    if (wid == 0) {
        int w = warpsum[lane];
#pragma unroll
        for (int off = 1; off < 32; off <<= 1) {
            int y = __shfl_up_sync(~0u, w, off);
            if (lane >= off) w += y;
        }
        warpsum[lane] = w;
    }
    __syncthreads();
    int run = x - tot + (wid ? warpsum[wid - 1] : 0);
    if (tid == 0) g_rowptr[0] = 0;
#pragma unroll
    for (int i = 0; i < 10; i++) {
        int idx = base + i;
        if (idx < N_NODES) {
            g_cursor[idx] = run;
            run += v[i];
            g_rowptr[idx + 1] = run;
            g_degf[idx] = (float)v[i];
        }
    }
}

__global__ void fill_kernel(const int* __restrict__ src,
                            const int* __restrict__ dst,
                            const float* __restrict__ ef)
{
    int e = blockIdx.x * blockDim.x + threadIdx.x;
    if (e >= N_EDGES) return;
    int d = dst[e];
    int pos = atomicAdd(&g_cursor[d], 1);
    g_ssrc[pos] = src[e];
#pragma unroll
    for (int q = 0; q < NBOND; q++)
        g_sef[(size_t)pos * NBOND + q] = ef[(size_t)e * NBOND + q];
}

// ---------------------------------------------------------------------------
// Aggregate (half2): ragg16[n] = fp16( sum relu(xa[src]+xb[n]+ef@W1c+b1) )
// 128 threads = 128 half2 lanes (256 channels); W1c column in 6 half2 regs.
// ---------------------------------------------------------------------------
#define NPC 8
#define CHE 32
__global__ void __launch_bounds__(128) aggregate_kernel(
    const __half2* __restrict__ xa2, const __half2* __restrict__ xb2,
    const float* __restrict__ w1c, const float* __restrict__ b1,
    __half2* __restrict__ ragg2)
{
    __shared__ int     s_src[CHE];
    __shared__ __half2 s_ef2[CHE][NBOND];

    int n0 = blockIdx.x * NPC;
    int c = threadIdx.x;           // half2 lane: channels 2c, 2c+1

    __half2 wreg[NBOND];
#pragma unroll
    for (int q = 0; q < NBOND; q++)
        wreg[q] = __floats2half2_rn(w1c[q * 256 + 2 * c],
                                    w1c[q * 256 + 2 * c + 1]);
    __half2 b12 = __floats2half2_rn(b1[2 * c], b1[2 * c + 1]);
    const __half2 zero2 = __float2half2_rn(0.f);

    for (int ni = 0; ni < NPC; ni++) {
        int n = n0 + ni;
        if (n >= N_NODES) break;
        __half2 base2 = __hadd2(b12, xb2[(size_t)n * 128 + c]);
        int beg = g_rowptr[n], end = g_rowptr[n + 1];
        float accx = 0.f, accy = 0.f;
        for (int b0 = beg; b0 < end; b0 += CHE) {
            int m = min(CHE, end - b0);
            __syncthreads();
            if (c < m) s_src[c] = g_ssrc[b0 + c];
            for (int i = c; i < m * NBOND; i += 128)
                s_ef2[i / NBOND][i % NBOND] =
                    __float2half2_rn(g_sef[(size_t)b0 * NBOND + i]);
            __syncthreads();
            for (int j = 0; j < m; j++) {
                __half2 t = __hadd2(xa2[(size_t)s_src[j] * 128 + c], base2);
#pragma unroll
                for (int q = 0; q < NBOND; q++)
                    t = __hfma2(s_ef2[j][q], wreg[q], t);
                t = __hmax2(t, zero2);
                float2 f = __half22float2(t);
                accx += f.x;
                accy += f.y;
            }
        }
        ragg2[(size_t)n * 128 + c] = __floats2half2_rn(accx, accy);
    }
}

// ---------------------------------------------------------------------------
// Launch
// ---------------------------------------------------------------------------
extern "C" void kernel_launch(void* const* d_in, const int* in_sizes, int n_in,
                              void* d_out, int out_size)
{
    const float* atom = (const float*)d_in[0];
    const int*   eidx = (const int*)d_in[1];
    const float* ef   = (const float*)d_in[2];
    const float* embw = (const float*)d_in[3];
    const float* embb = (const float*)d_in[4];
    const float* mw1  = (const float*)d_in[5];
    const float* mb1  = (const float*)d_in[6];
    const float* mw2  = (const float*)d_in[7];
    const float* mb2  = (const float*)d_in[8];
    const float* uw1  = (const float*)d_in[9];
    const float* ub1  = (const float*)d_in[10];
    const float* uw2  = (const float*)d_in[11];
    const float* ub2  = (const float*)d_in[12];
    const float* rw1  = (const float*)d_in[13];
    const float* rb1  = (const float*)d_in[14];
    const float* rw2  = (const float*)d_in[15];
    const float* rb2  = (const float*)d_in[16];
    const float* rw3  = (const float*)d_in[17];
    const float* rb3  = (const float*)d_in[18];

    const int* src = eidx;
    const int* dst = eidx + N_EDGES;

    float *px, *pxa, *pxb, *pagg, *pt1, *ph, *pdegf, *pvb;
    int* pdeg;
    __half* pwt;
    cudaGetSymbolAddress((void**)&px,    g_x);
    cudaGetSymbolAddress((void**)&pxa,   g_xa);
    cudaGetSymbolAddress((void**)&pxb,   g_xb);
    cudaGetSymbolAddress((void**)&pagg,  g_agg);
    cudaGetSymbolAddress((void**)&pt1,   g_t1);
    cudaGetSymbolAddress((void**)&ph,    g_h);
    cudaGetSymbolAddress((void**)&pdeg,  g_deg);
    cudaGetSymbolAddress((void**)&pdegf, g_degf);
    cudaGetSymbolAddress((void**)&pvb,   g_vbias);
    cudaGetSymbolAddress((void**)&pwt,   g_wt);

    const int SM4 = 2 * (4 * 32 * 80 + 10240);   // 40960
    const int SM5 = 2 * (5 * 32 * 80 + 10240);   // 46080
    static bool attr_done = false;
    if (!attr_done) {
        cudaFuncSetAttribute(tgemm<4>,
                             cudaFuncAttributeMaxDynamicSharedMemorySize, SM4);
        cudaFuncSetAttribute(tgemm<5>,
                             cudaFuncAttributeMaxDynamicSharedMemorySize, SM5);
        attr_done = true;
    }

    static bool inited = false;
    static cudaStream_t sA, sB;
    static cudaEvent_t evRoot, evA, evB;
    if (!inited) {
        cudaStreamCreateWithFlags(&sA, cudaStreamNonBlocking);
        cudaStreamCreateWithFlags(&sB, cudaStreamNonBlocking);
        cudaEventCreateWithFlags(&evRoot, cudaEventDisableTiming);
        cudaEventCreateWithFlags(&evA, cudaEventDisableTiming);
        cudaEventCreateWithFlags(&evB, cudaEventDisableTiming);
        inited = true;
    }

    // d_out zero issued first (off the tail)
    cudaMemsetAsync(d_out, 0, sizeof(float));

    // fork
    cudaEventRecord(evRoot, 0);
    cudaStreamWaitEvent(sA, evRoot, 0);
    cudaStreamWaitEvent(sB, evRoot, 0);

    // stream A: weight critical path (combine -> wsplit)
    combine_kernel<<<dim3(2, 2, NCOMB), 256, 0, sA>>>(mw1, uw1, mw2, uw2, rw1);
    wsplit_kernel<<<dim3(8, 8, NSLOTS), dim3(32, 8), 0, sA>>>(mw1, uw1, rw2, pwt);
    cudaEventRecord(evA, sA);

    // stream B: CSR pipeline + vbias (off the weight critical path)
    cudaMemsetAsync(pdeg, 0, sizeof(int) * N_NODES, sB);
    count_kernel<<<(N_EDGES + 255) / 256, 256, 0, sB>>>(dst);
    scan_kernel<<<1, 1024, 0, sB>>>();
    fill_kernel<<<(N_EDGES + 255) / 256, 256, 0, sB>>>(src, dst, ef);
    vbias_kernel<<<NCOMB, 256, 0, sB>>>(mw1, uw1, rw1, mb2, ub2, rb1);
    cudaEventRecord(evB, sB);

    // main stream: embed (overlaps setup), then join weight pipeline
    embed_kernel<<<(N_NODES + EMB_NODES - 1) / EMB_NODES, 256>>>(
        atom, embw, embb, (__half*)px);
    cudaStreamWaitEvent(0, evA, 0);

    const int MT5 = (N_NODES + 159) / 160;     // 63
    dim3 gG3(2, (N_NODES + 127) / 128, 3);     // tgemm<4>, 474 CTAs
    dim3 gS(2, MT5, 1);                        // tgemm<5>, 126 CTAs
    const int AGG_BLK = (N_NODES + NPC - 1) / NPC;  // 1250

    // layer 0 inputs: xa(fp16),xb(fp16),t1(fp32) from x0(fp16)
    tgemm<4><<<gG3, 256, SM4>>>((const __half*)px, pwt, 0, 1, 2,
                                nullptr, nullptr, nullptr,
                                nullptr, nullptr, nullptr,
                                pxa, pxb, pt1, N_NODES, 256, 16 | 32);

    // join CSR + vbias pipeline before first aggregate
    cudaStreamWaitEvent(0, evB, 0);

    for (int l = 0; l < NLAYERS; l++) {
        const float* W1c = mw1 + (size_t)l * 518 * HID + 512 * HID;

        // ragg16[n] = fp16( sum relu(xa16[src]+xb16[n]+ef@W1c+b1) )
        aggregate_kernel<<<AGG_BLK, 128>>>((const __half2*)pxa,
                                           (const __half2*)pxb, W1c,
                                           mb1 + (size_t)l * HID,
                                           (__half2*)pagg);

        // h(fp16) = relu(ragg@(W2@U1b) + deg*(b2@U1b) + ub1 + t1)
        tgemm<5><<<gS, 256, SM5>>>((const __half*)pagg, pwt, 3 + l, 0, 0,
                                   ub1 + (size_t)l * HID, nullptr, nullptr,
                                   pvb + (size_t)l * 256, pdegf, pt1,
                                   ph, nullptr, nullptr, N_NODES, 256,
                                   1 | 2 | 4 | 8 | 16);

        if (l < NLAYERS - 1) {
            // next xa(fp16),xb(fp16),t1(fp32) from h(fp16), combined weights
            int cb = 6 + 3 * l;
            tgemm<4><<<gG3, 256, SM4>>>((const __half*)ph, pwt,
                                        9 + 3 * l, 10 + 3 * l, 11 + 3 * l,
                                        pvb + (size_t)cb * 256,
                                        pvb + (size_t)(cb + 1) * 256,
                                        pvb + (size_t)(cb + 2) * 256,
                                        nullptr, nullptr, nullptr,
                                        pxa, pxb, pt1, N_NODES, 256,
                                        4 | 16 | 32);
        }
    }

    // readout r1(fp16) = relu(h@(U2_5@rw1) + (ub2_5@rw1 + rb1))
    tgemm<5><<<gS, 256, SM5>>>((const __half*)ph, pwt, 24, 0, 0,
                               pvb + (size_t)21 * 256, nullptr, nullptr,
                               nullptr, nullptr, nullptr,
                               pt1, nullptr, nullptr, N_NODES, 256, 1 | 4 | 16);
    // r2 fused with readout: out = mean( relu(r1@rw2 + rb2) . rw3 ) + rb3
    dim3 gR(1, MT5, 1);
    tgemm<5><<<gR, 256, SM5>>>((const __half*)pt1, pwt, 25, 0, 0,
                               rb2, nullptr, rb3,
                               rw3, nullptr, nullptr,
                               (float*)d_out, nullptr, nullptr, N_NODES, 128,
                               1 | 4 | 64);
}

// round 17
// speedup vs baseline: 1.5966x; 1.0451x over previous
#include <cuda_runtime.h>
#include <cuda_fp16.h>
#include <cstdint>

#define N_NODES 10000
#define N_EDGES 160000
#define HID 256
#define NBOND 6
#define NATOM 62
#define NLAYERS 6
#define NSLOTS 26
#define NCOMB 22

// ---------------- scratch (device globals; no allocation allowed) ----------
__device__ float g_x[N_NODES * HID];    // x0 as __half
__device__ float g_xa[N_NODES * HID];   // xa as __half
__device__ float g_xb[N_NODES * HID];   // xb as __half
__device__ float g_agg[N_NODES * HID];  // ragg as __half
__device__ float g_t1[N_NODES * HID];   // t1 fp32 / r1 as __half
__device__ float g_h[N_NODES * HID];    // h as __half

__device__ int   g_deg[N_NODES];
__device__ int   g_rowptr[N_NODES + 1];
__device__ int   g_cursor[N_NODES];
__device__ int   g_ssrc[N_EDGES];
__device__ float g_sef[N_EDGES * NBOND];
__device__ float g_degf[N_NODES];

__device__ float g_wcomb[NCOMB * 65536];
__device__ float g_vbias[NCOMB * 256];
__device__ __half g_wt[NSLOTS * 256 * 256];

// ---------------- helpers ---------------------------------------------------
__device__ __forceinline__ uint32_t smem_u32(const void* p) {
    uint32_t a;
    asm("{ .reg .u64 t; cvta.to.shared.u64 t, %1; cvt.u32.u64 %0, t; }"
        : "=r"(a) : "l"(p));
    return a;
}
__device__ __forceinline__ void ldm_x4(uint32_t* r, uint32_t addr) {
    asm volatile("ldmatrix.sync.aligned.m8n8.x4.shared.b16 {%0,%1,%2,%3}, [%4];"
                 : "=r"(r[0]), "=r"(r[1]), "=r"(r[2]), "=r"(r[3]) : "r"(addr));
}
__device__ __forceinline__ void mma_f16(float* c, const uint32_t* a,
                                        uint32_t b0, uint32_t b1) {
    asm volatile(
        "mma.sync.aligned.m16n8k16.row.col.f32.f16.f16.f32 "
        "{%0,%1,%2,%3}, {%4,%5,%6,%7}, {%8,%9}, {%0,%1,%2,%3};"
        : "+f"(c[0]), "+f"(c[1]), "+f"(c[2]), "+f"(c[3])
        : "r"(a[0]), "r"(a[1]), "r"(a[2]), "r"(a[3]), "r"(b0), "r"(b1));
}
__device__ __forceinline__ void cp16(uint32_t dst, const void* src) {
    asm volatile("cp.async.cg.shared.global [%0], [%1], 16;"
                 :: "r"(dst), "l"(src));
}
__device__ __forceinline__ void cp_commit() {
    asm volatile("cp.async.commit_group;" ::: "memory");
}
__device__ __forceinline__ void cp_wait0() {
    asm volatile("cp.async.wait_group 0;" ::: "memory");
}
// PDL (sm_90+; plain feature, no 'a' suffix)
__device__ __forceinline__ void pdl_wait() {
    asm volatile("griddepcontrol.wait;" ::: "memory");
}
__device__ __forceinline__ void pdl_trigger() {
    asm volatile("griddepcontrol.launch_dependents;" ::: "memory");
}

// ---------------------------------------------------------------------------
// Combo source pointers:
//  c in [0,6):   P = W2_l (mw2),  Q = U1b_l          (WU_l = W2@U1b)
//  c in [6,21):  P = U2_m (uw2),  Q in {W1a,W1b,U1a} of layer m+1
//  c == 21:      P = U2_5,        Q = rw1
// ---------------------------------------------------------------------------
__device__ __forceinline__ const float* combo_Q(
    int c, const float* mw1, const float* uw1, const float* rw1)
{
    if (c < 6) return uw1 + (size_t)c * 131072 + 65536;
    if (c < 21) {
        int m = (c - 6) / 3, t = (c - 6) % 3;
        int l = m + 1;
        if (t == 0) return mw1 + (size_t)l * 518 * 256;
        if (t == 1) return mw1 + (size_t)l * 518 * 256 + 65536;
        return uw1 + (size_t)l * 131072;
    }
    return rw1;
}

// fp32 setup GEMM: g_wcomb[c] = P_c @ Q_c   (256x256x256), grid (2,2,22)
__global__ void __launch_bounds__(256) combine_kernel(
    const float* __restrict__ mw1, const float* __restrict__ uw1,
    const float* __restrict__ mw2, const float* __restrict__ uw2,
    const float* __restrict__ rw1)
{
    int c = blockIdx.z;
    const float* P = (c < 6) ? mw2 + (size_t)c * 65536
                   : (c < 21) ? uw2 + (size_t)((c - 6) / 3) * 65536
                              : uw2 + (size_t)5 * 65536;
    const float* Q = combo_Q(c, mw1, uw1, rw1);
    float* C = g_wcomb + (size_t)c * 65536;

    __shared__ float As[16][128];
    __shared__ float Ws[16][128];
    int col0 = blockIdx.x * 128, row0 = blockIdx.y * 128;
    int tid = threadIdx.x;
    int tx = tid & 15, ty = tid >> 4;

    float acc[8][8];
#pragma unroll
    for (int i = 0; i < 8; i++)
#pragma unroll
        for (int j = 0; j < 8; j++) acc[i][j] = 0.f;

    int ar = tid >> 2, ac = (tid & 3) << 2;
    int wr = tid >> 5, wc = (tid & 31) << 2;

    for (int kt = 0; kt < 256; kt += 16) {
#pragma unroll
        for (int i = 0; i < 2; i++) {
            int r = ar + i * 64;
            float4 v = *(const float4*)(P + (size_t)(row0 + r) * 256 + kt + ac);
            As[ac + 0][r] = v.x; As[ac + 1][r] = v.y;
            As[ac + 2][r] = v.z; As[ac + 3][r] = v.w;
        }
#pragma unroll
        for (int i = 0; i < 2; i++) {
            int r = wr + i * 8;
            *(float4*)&Ws[r][wc] =
                *(const float4*)(Q + (size_t)(kt + r) * 256 + col0 + wc);
        }
        __syncthreads();
#pragma unroll
        for (int kk = 0; kk < 16; kk++) {
            float4 a0 = *(const float4*)&As[kk][ty * 4];
            float4 a1 = *(const float4*)&As[kk][64 + ty * 4];
            float4 w0 = *(const float4*)&Ws[kk][tx * 4];
            float4 w1 = *(const float4*)&Ws[kk][64 + tx * 4];
            float af[8] = {a0.x, a0.y, a0.z, a0.w, a1.x, a1.y, a1.z, a1.w};
            float wf[8] = {w0.x, w0.y, w0.z, w0.w, w1.x, w1.y, w1.z, w1.w};
#pragma unroll
            for (int i = 0; i < 8; i++)
#pragma unroll
                for (int j = 0; j < 8; j++)
                    acc[i][j] = fmaf(af[i], wf[j], acc[i][j]);
        }
        __syncthreads();
    }
#pragma unroll
    for (int ih = 0; ih < 2; ih++)
#pragma unroll
        for (int i = 0; i < 4; i++) {
            int r = row0 + ih * 64 + ty * 4 + i;
#pragma unroll
            for (int jh = 0; jh < 2; jh++)
#pragma unroll
                for (int j = 0; j < 4; j++)
                    C[(size_t)r * 256 + col0 + jh * 64 + tx * 4 + j] =
                        acc[ih * 4 + i][jh * 4 + j];
        }
}

// combined bias vectors: g_vbias[c] = b_c @ Q_c (+ rb1 for c==21), grid (22)
__global__ void __launch_bounds__(256) vbias_kernel(
    const float* __restrict__ mw1, const float* __restrict__ uw1,
    const float* __restrict__ rw1, const float* __restrict__ mb2,
    const float* __restrict__ ub2, const float* __restrict__ rb1)
{
    int c = blockIdx.x;
    const float* b = (c < 6) ? mb2 + (size_t)c * 256
                   : (c < 21) ? ub2 + (size_t)((c - 6) / 3) * 256
                              : ub2 + (size_t)5 * 256;
    const float* Q = combo_Q(c, mw1, uw1, rw1);
    int n = threadIdx.x;
    float s = 0.f;
    for (int k = 0; k < 256; k++) s = fmaf(b[k], Q[(size_t)k * 256 + n], s);
    if (c == 21) s += rb1[n];
    g_vbias[(size_t)c * 256 + n] = s;
}

// ---------------------------------------------------------------------------
// Weight transpose to fp16: pool[z][n][k] = fp16(S_z[k][n])
// ---------------------------------------------------------------------------
__global__ void wsplit_kernel(
    const float* __restrict__ mw1, const float* __restrict__ uw1,
    const float* __restrict__ rw2, __half* __restrict__ wt)
{
    int z = blockIdx.z;
    const float* W;
    int N = 256;
    if (z < 2)       W = mw1 + (size_t)z * 65536;
    else if (z == 2) W = uw1;
    else if (z < 25) W = g_wcomb + (size_t)(z - 3) * 65536;
    else { W = rw2; N = 128; }

    int k0 = blockIdx.x * 32, n0 = blockIdx.y * 32;
    if (n0 >= N) return;
    __shared__ float t[32][33];
    for (int i = threadIdx.y; i < 32; i += 8)
        t[i][threadIdx.x] = W[(size_t)(k0 + i) * N + n0 + threadIdx.x];
    __syncthreads();
    size_t base = (size_t)z * 65536;
    for (int i = threadIdx.y; i < 32; i += 8)
        wt[base + (size_t)(n0 + i) * 256 + k0 + threadIdx.x] =
            __float2half(t[threadIdx.x][i]);
}

// ---------------------------------------------------------------------------
// fp16 GEMM via mma.sync, 1-term, double-buffered cp.async, PDL wait/trigger.
// Tile (MI*32) x 128, 8 warps. MI=4: 2 CTAs/SM; MI=5: 1 CTA/SM.
// flags: 1=RELU 2=ADDC 4=BIAS 8=ROWB(rowscale*rbias)
//        16=HALF_OUT(bz0) 32=HALF_OUT(bz1)
//        64=DOT_OUT(bz0): no store; out += sum(v*rbias)/N (+b2p[0] once)
// ---------------------------------------------------------------------------
template <int MI>
__global__ void __launch_bounds__(256, (MI == 4) ? 2 : 1) tgemm(
    const __half* __restrict__ A,
    const __half* __restrict__ wt,
    int s0, int s1, int s2,
    const float* __restrict__ b0p, const float* __restrict__ b1p,
    const float* __restrict__ b2p,
    const float* __restrict__ rbias, const float* __restrict__ rowscale,
    const float* __restrict__ Cprev,
    float* C0, float* C1, float* C2,
    int M, int ldc, int flags)
{
    constexpr int TM = MI * 32;
    constexpr int WBASE = TM * 80;
    constexpr int BUFSZ = WBASE + 10240;

    extern __shared__ __align__(16) char smem[];

    int bz = blockIdx.z;
    int slot = (bz == 0) ? s0 : (bz == 1 ? s1 : s2);
    float* C = (bz == 0) ? C0 : (bz == 1 ? C1 : C2);
    const float* bias = (bz == 0) ? b0p : (bz == 1 ? b1p : b2p);
    const __half* Wp = wt + (size_t)slot * 65536;
    bool half_out = ((flags & 16) && bz == 0) || ((flags & 32) && bz == 1);
    bool dot_out = (flags & 64) && (bz == 0);

    uint32_t sb = smem_u32(smem);
    int tid = threadIdx.x;
    int lane = tid & 31, wid = tid >> 5;
    int wr = wid >> 2, wc = wid & 3;
    int row0 = blockIdx.y * TM, col0 = blockIdx.x * 128;

    float acc[MI][4][4];
#pragma unroll
    for (int i = 0; i < MI; i++)
#pragma unroll
        for (int j = 0; j < 4; j++)
#pragma unroll
            for (int k = 0; k < 4; k++) acc[i][j][k] = 0.f;

    int a_row = lane & 15;
    int a_kh = (lane >> 4) * 8;
    int bg = lane >> 3;
    int b_n = (lane & 7) + (bg >> 1) * 8;
    int b_kh = (bg & 1) * 8;

    int lrow = tid >> 1;
    int lhalf = tid & 1;
    size_t wgoff = (size_t)(col0 + lrow) * 256 + lhalf * 16;
    uint32_t wsoff = (uint32_t)(lrow * 80 + lhalf * 32);

    pdl_wait();  // predecessor grids complete + flushed before first read

#define ISSUE_AW(ch, buf)                                                   \
    do {                                                                    \
        uint32_t bb_ = sb + (buf) * BUFSZ;                                  \
        for (int idx = tid; idx < TM * 4; idx += 256) {                     \
            int r_ = idx >> 2, seg_ = idx & 3;                              \
            cp16(bb_ + (uint32_t)(r_ * 80 + seg_ * 16),                     \
                 A + (size_t)(row0 + r_) * 256 + (ch) * 32 + seg_ * 8);     \
        }                                                                   \
        const __half* pw_ = Wp + wgoff + (ch) * 32;                         \
        cp16(bb_ + WBASE + wsoff, pw_);                                     \
        cp16(bb_ + WBASE + wsoff + 16, pw_ + 8);                            \
    } while (0)

    ISSUE_AW(0, 0);
    cp_commit();
    cp_wait0();
    __syncthreads();

#pragma unroll 2
    for (int ch = 0; ch < 8; ch++) {
        int buf = ch & 1;
        if (ch < 7) {
            ISSUE_AW(ch + 1, buf ^ 1);
            cp_commit();
        }
        uint32_t base = sb + buf * BUFSZ;
#pragma unroll
        for (int ks = 0; ks < 2; ks++) {
            uint32_t Af[MI][4], Bf[2][4];
            uint32_t acol = (uint32_t)((ks * 16 + a_kh) * 2);
            uint32_t bcol = (uint32_t)((ks * 16 + b_kh) * 2);
#pragma unroll
            for (int nj = 0; nj < 2; nj++)
                ldm_x4(Bf[nj], base + WBASE +
                               (uint32_t)((wc * 32 + nj * 16 + b_n) * 80) + bcol);
#pragma unroll
            for (int mi = 0; mi < MI; mi++)
                ldm_x4(Af[mi], base +
                               (uint32_t)((wr * (MI * 16) + mi * 16 + a_row) * 80) + acol);
#pragma unroll
            for (int mi = 0; mi < MI; mi++)
#pragma unroll
                for (int ni = 0; ni < 4; ni++) {
                    int nj = ni >> 1, off = (ni & 1) * 2;
                    mma_f16(acc[mi][ni], Af[mi], Bf[nj][off], Bf[nj][off + 1]);
                }
        }
        if (ch < 7) {
            cp_wait0();
            __syncthreads();
        }
    }

    pdl_trigger();  // mainloop done; let dependents roll out over the epilogue

    // ---- epilogue ----
    float dot = 0.f;
#pragma unroll
    for (int mi = 0; mi < MI; mi++) {
        int m0 = row0 + wr * (MI * 16) + mi * 16 + (lane >> 2);
        int m1 = m0 + 8;
        float rs0 = 0.f, rs1 = 0.f;
        if (flags & 8) {
            if (m0 < M) rs0 = rowscale[m0];
            if (m1 < M) rs1 = rowscale[m1];
        }
#pragma unroll
        for (int ni = 0; ni < 4; ni++) {
            int nc = col0 + wc * 32 + ni * 8 + (lane & 3) * 2;
            float b0 = 0.f, b1 = 0.f, r0b = 0.f, r1b = 0.f;
            if (flags & 4) { b0 = bias[nc]; b1 = bias[nc + 1]; }
            if (flags & 8) { r0b = rbias[nc]; r1b = rbias[nc + 1]; }
            float* a = acc[mi][ni];
            if (m0 < M) {
                float v0 = a[0] + b0, v1 = a[1] + b1;
                if (flags & 8) { v0 = fmaf(rs0, r0b, v0); v1 = fmaf(rs0, r1b, v1); }
                if (flags & 2) {
                    v0 += Cprev[(size_t)m0 * 256 + nc];
                    v1 += Cprev[(size_t)m0 * 256 + nc + 1];
                }
                if (flags & 1) { v0 = fmaxf(v0, 0.f); v1 = fmaxf(v1, 0.f); }
                if (dot_out) {
                    dot += v0 * rbias[nc] + v1 * rbias[nc + 1];
                } else if (half_out)
                    *(__half2*)((__half*)C + (size_t)m0 * ldc + nc) =
                        __floats2half2_rn(v0, v1);
                else
                    *(float2*)(C + (size_t)m0 * ldc + nc) = make_float2(v0, v1);
            }
            if (m1 < M) {
                float v0 = a[2] + b0, v1 = a[3] + b1;
                if (flags & 8) { v0 = fmaf(rs1, r0b, v0); v1 = fmaf(rs1, r1b, v1); }
                if (flags & 2) {
                    v0 += Cprev[(size_t)m1 * 256 + nc];
                    v1 += Cprev[(size_t)m1 * 256 + nc + 1];
                }
                if (flags & 1) { v0 = fmaxf(v0, 0.f); v1 = fmaxf(v1, 0.f); }
                if (dot_out) {
                    dot += v0 * rbias[nc] + v1 * rbias[nc + 1];
                } else if (half_out)
                    *(__half2*)((__half*)C + (size_t)m1 * ldc + nc) =
                        __floats2half2_rn(v0, v1);
                else
                    *(float2*)(C + (size_t)m1 * ldc + nc) = make_float2(v0, v1);
            }
        }
    }
    if (dot_out) {
        float* sred = (float*)smem;
        __syncthreads();
        sred[tid] = dot;
        __syncthreads();
        for (int st = 128; st > 0; st >>= 1) {
            if (tid < st) sred[tid] += sred[tid + st];
            __syncthreads();
        }
        if (tid == 0) {
            float tot = sred[0] * (1.0f / N_NODES);
            if (blockIdx.y == 0) tot += b2p[0];
            atomicAdd(C, tot);
        }
    }
#undef ISSUE_AW
}

// ---------------------------------------------------------------------------
// Embed: x0 = fp16(atom @ embed_w + embed_b)
// ---------------------------------------------------------------------------
#define EMB_NODES 16
__global__ void __launch_bounds__(256) embed_kernel(
    const float* __restrict__ atom, const float* __restrict__ w,
    const float* __restrict__ b, __half* __restrict__ x16)
{
    __shared__ float s_af[EMB_NODES][NATOM];
    int n0 = blockIdx.x * EMB_NODES;
    int tid = threadIdx.x;
    for (int i = tid; i < EMB_NODES * NATOM; i += 256) {
        int r = i / NATOM, c = i % NATOM;
        int n = n0 + r;
        s_af[r][c] = (n < N_NODES) ? atom[(size_t)n * NATOM + c] : 0.f;
    }
    __syncthreads();
    int j = tid;
    float acc[EMB_NODES];
    float bj = b[j];
#pragma unroll
    for (int r = 0; r < EMB_NODES; r++) acc[r] = bj;
    for (int k = 0; k < NATOM; k++) {
        float wv = w[k * HID + j];
#pragma unroll
        for (int r = 0; r < EMB_NODES; r++) acc[r] = fmaf(s_af[r][k], wv, acc[r]);
    }
#pragma unroll
    for (int r = 0; r < EMB_NODES; r++) {
        int n = n0 + r;
        if (n < N_NODES) x16[(size_t)n * HID + j] = __float2half(acc[r]);
    }
}

// ---------------------------------------------------------------------------
// CSR build
// ---------------------------------------------------------------------------
__global__ void count_kernel(const int* __restrict__ dst)
{
    int e = blockIdx.x * blockDim.x + threadIdx.x;
    if (e < N_EDGES) atomicAdd(&g_deg[dst[e]], 1);
}

__global__ void __launch_bounds__(1024) scan_kernel()
{
    __shared__ int sdeg[10240];
    __shared__ int warpsum[32];
    int tid = threadIdx.x;
#pragma unroll
    for (int i = 0; i < 10; i++) {
        int idx = i * 1024 + tid;
        sdeg[idx] = (idx < N_NODES) ? g_deg[idx] : 0;
    }
    __syncthreads();
    int base = tid * 10;
    int v[10];
    int tot = 0;
#pragma unroll
    for (int i = 0; i < 10; i++) {
        v[i] = sdeg[base + i];
        tot += v[i];
    }
    int lane = tid & 31, wid = tid >> 5;
    int x = tot;
#pragma unroll
    for (int off = 1; off < 32; off <<= 1) {
        int y = __shfl_up_sync(~0u, x, off);
        if (lane >= off) x += y;
    }
    if (lane == 31) warpsum[wid] = x;
    __syncthreads();
    if (wid == 0) {
        int w = warpsum[lane];
#pragma unroll
        for (int off = 1; off < 32; off <<= 1) {
            int y = __shfl_up_sync(~0u, w, off);
            if (lane >= off) w += y;
        }
        warpsum[lane] = w;
    }
    __syncthreads();
    int run = x - tot + (wid ? warpsum[wid - 1] : 0);
    if (tid == 0) g_rowptr[0] = 0;
#pragma unroll
    for (int i = 0; i < 10; i++) {
        int idx = base + i;
        if (idx < N_NODES) {
            g_cursor[idx] = run;
            run += v[i];
            g_rowptr[idx + 1] = run;
            g_degf[idx] = (float)v[i];
        }
    }
}

__global__ void fill_kernel(const int* __restrict__ src,
                            const int* __restrict__ dst,
                            const float* __restrict__ ef)
{
    int e = blockIdx.x * blockDim.x + threadIdx.x;
    if (e >= N_EDGES) return;
    int d = dst[e];
    int pos = atomicAdd(&g_cursor[d], 1);
    g_ssrc[pos] = src[e];
#pragma unroll
    for (int q = 0; q < NBOND; q++)
        g_sef[(size_t)pos * NBOND + q] = ef[(size_t)e * NBOND + q];
}

// ---------------------------------------------------------------------------
// Aggregate (half2, contiguous 8-node edge-range staging):
//   ragg16[n] = fp16( sum relu(xa[src]+xb[n]+ef@W1c+b1) )
// 128 threads = 128 half2 lanes (256 channels).
// ---------------------------------------------------------------------------
#define NPC 8
#define ECAP 192
__global__ void __launch_bounds__(128) aggregate_kernel(
    const __half2* __restrict__ xa2, const __half2* __restrict__ xb2,
    const float* __restrict__ w1c, const float* __restrict__ b1,
    __half2* __restrict__ ragg2)
{
    __shared__ int     s_src[ECAP];
    __shared__ __half2 s_ef2[ECAP][NBOND];

    int n0 = blockIdx.x * NPC;
    int c = threadIdx.x;           // half2 lane: channels 2c, 2c+1

    pdl_wait();

    __half2 wreg[NBOND];
#pragma unroll
    for (int q = 0; q < NBOND; q++)
        wreg[q] = __floats2half2_rn(w1c[q * 256 + 2 * c],
                                    w1c[q * 256 + 2 * c + 1]);
    __half2 b12 = __floats2half2_rn(b1[2 * c], b1[2 * c + 1]);
    const __half2 zero2 = __float2half2_rn(0.f);

    int rs[NPC + 1];
#pragma unroll
    for (int i = 0; i <= NPC; i++)
        rs[i] = g_rowptr[min(n0 + i, N_NODES)];

    __half2 base2[NPC];
    float accx[NPC], accy[NPC];
#pragma unroll
    for (int ni = 0; ni < NPC; ni++) {
        int n = n0 + ni;
        base2[ni] = (n < N_NODES) ? __hadd2(b12, xb2[(size_t)n * 128 + c])
                                  : zero2;
        accx[ni] = 0.f;
        accy[ni] = 0.f;
    }

    int beg = rs[0], end = rs[NPC];
    for (int b0 = beg; b0 < end; b0 += ECAP) {
        int m = min(ECAP, end - b0);
        __syncthreads();
        for (int i = c; i < m; i += 128) s_src[i] = g_ssrc[b0 + i];
        for (int i = c; i < m * NBOND; i += 128)
            s_ef2[i / NBOND][i % NBOND] =
                __float2half2_rn(g_sef[(size_t)b0 * NBOND + i]);
        __syncthreads();
#pragma unroll
        for (int ni = 0; ni < NPC; ni++) {
            int lo = (rs[ni] > b0) ? rs[ni] - b0 : 0;
            int hi = min(rs[ni + 1], b0 + m) - b0;
            for (int j = lo; j < hi; j++) {
                __half2 t = __hadd2(xa2[(size_t)s_src[j] * 128 + c],
                                    base2[ni]);
#pragma unroll
                for (int q = 0; q < NBOND; q++)
                    t = __hfma2(s_ef2[j][q], wreg[q], t);
                t = __hmax2(t, zero2);
                float2 f = __half22float2(t);
                accx[ni] += f.x;
                accy[ni] += f.y;
            }
        }
    }

    pdl_trigger();

#pragma unroll
    for (int ni = 0; ni < NPC; ni++) {
        int n = n0 + ni;
        if (n < N_NODES)
            ragg2[(size_t)n * 128 + c] = __floats2half2_rn(accx[ni], accy[ni]);
    }
}

// ---------------------------------------------------------------------------
// Launch
// ---------------------------------------------------------------------------
extern "C" void kernel_launch(void* const* d_in, const int* in_sizes, int n_in,
                              void* d_out, int out_size)
{
    const float* atom = (const float*)d_in[0];
    const int*   eidx = (const int*)d_in[1];
    const float* ef   = (const float*)d_in[2];
    const float* embw = (const float*)d_in[3];
    const float* embb = (const float*)d_in[4];
    const float* mw1  = (const float*)d_in[5];
    const float* mb1  = (const float*)d_in[6];
    const float* mw2  = (const float*)d_in[7];
    const float* mb2  = (const float*)d_in[8];
    const float* uw1  = (const float*)d_in[9];
    const float* ub1  = (const float*)d_in[10];
    const float* uw2  = (const float*)d_in[11];
    const float* ub2  = (const float*)d_in[12];
    const float* rw1  = (const float*)d_in[13];
    const float* rb1  = (const float*)d_in[14];
    const float* rw2  = (const float*)d_in[15];
    const float* rb2  = (const float*)d_in[16];
    const float* rw3  = (const float*)d_in[17];
    const float* rb3  = (const float*)d_in[18];

    const int* src = eidx;
    const int* dst = eidx + N_EDGES;

    float *px, *pxa, *pxb, *pagg, *pt1, *ph, *pdegf, *pvb;
    int* pdeg;
    __half* pwt;
    cudaGetSymbolAddress((void**)&px,    g_x);
    cudaGetSymbolAddress((void**)&pxa,   g_xa);
    cudaGetSymbolAddress((void**)&pxb,   g_xb);
    cudaGetSymbolAddress((void**)&pagg,  g_agg);
    cudaGetSymbolAddress((void**)&pt1,   g_t1);
    cudaGetSymbolAddress((void**)&ph,    g_h);
    cudaGetSymbolAddress((void**)&pdeg,  g_deg);
    cudaGetSymbolAddress((void**)&pdegf, g_degf);
    cudaGetSymbolAddress((void**)&pvb,   g_vbias);
    cudaGetSymbolAddress((void**)&pwt,   g_wt);

    const int SM4 = 2 * (4 * 32 * 80 + 10240);   // 40960
    const int SM5 = 2 * (5 * 32 * 80 + 10240);   // 46080
    static bool attr_done = false;
    if (!attr_done) {
        cudaFuncSetAttribute(tgemm<4>,
                             cudaFuncAttributeMaxDynamicSharedMemorySize, SM4);
        cudaFuncSetAttribute(tgemm<5>,
                             cudaFuncAttributeMaxDynamicSharedMemorySize, SM5);
        attr_done = true;
    }

    static bool inited = false;
    static cudaStream_t sA, sB;
    static cudaEvent_t evRoot, evA, evB;
    if (!inited) {
        cudaStreamCreateWithFlags(&sA, cudaStreamNonBlocking);
        cudaStreamCreateWithFlags(&sB, cudaStreamNonBlocking);
        cudaEventCreateWithFlags(&evRoot, cudaEventDisableTiming);
        cudaEventCreateWithFlags(&evA, cudaEventDisableTiming);
        cudaEventCreateWithFlags(&evB, cudaEventDisableTiming);
        inited = true;
    }

    // PDL launch config (legacy default stream)
    cudaLaunchAttribute pdlAttr[1];
    pdlAttr[0].id = cudaLaunchAttributeProgrammaticStreamSerialization;
    pdlAttr[0].val.programmaticStreamSerializationAllowed = 1;
    cudaLaunchConfig_t cfg4 = {};
    cfg4.blockDim = dim3(256, 1, 1);
    cfg4.dynamicSmemBytes = SM4;
    cfg4.stream = 0;
    cfg4.attrs = pdlAttr;
    cfg4.numAttrs = 1;
    cudaLaunchConfig_t cfg5 = cfg4;
    cfg5.dynamicSmemBytes = SM5;
    cudaLaunchConfig_t cfgA = {};
    cfgA.blockDim = dim3(128, 1, 1);
    cfgA.dynamicSmemBytes = 0;
    cfgA.stream = 0;
    cfgA.attrs = pdlAttr;
    cfgA.numAttrs = 1;

    // d_out zero issued first (off the tail)
    cudaMemsetAsync(d_out, 0, sizeof(float));

    // fork
    cudaEventRecord(evRoot, 0);
    cudaStreamWaitEvent(sA, evRoot, 0);
    cudaStreamWaitEvent(sB, evRoot, 0);

    // stream A: weight critical path (combine -> wsplit)
    combine_kernel<<<dim3(2, 2, NCOMB), 256, 0, sA>>>(mw1, uw1, mw2, uw2, rw1);
    wsplit_kernel<<<dim3(8, 8, NSLOTS), dim3(32, 8), 0, sA>>>(mw1, uw1, rw2, pwt);
    cudaEventRecord(evA, sA);

    // stream B: CSR pipeline + vbias (off the weight critical path)
    cudaMemsetAsync(pdeg, 0, sizeof(int) * N_NODES, sB);
    count_kernel<<<(N_EDGES + 255) / 256, 256, 0, sB>>>(dst);
    scan_kernel<<<1, 1024, 0, sB>>>();
    fill_kernel<<<(N_EDGES + 255) / 256, 256, 0, sB>>>(src, dst, ef);
    vbias_kernel<<<NCOMB, 256, 0, sB>>>(mw1, uw1, rw1, mb2, ub2, rb1);
    cudaEventRecord(evB, sB);

    // main stream: embed (overlaps setup), then join weight pipeline
    embed_kernel<<<(N_NODES + EMB_NODES - 1) / EMB_NODES, 256>>>(
        atom, embw, embb, (__half*)px);
    cudaStreamWaitEvent(0, evA, 0);

    const int MT5 = (N_NODES + 159) / 160;     // 63
    dim3 gG3(2, (N_NODES + 127) / 128, 3);     // tgemm<4>, 474 CTAs
    dim3 gS(2, MT5, 1);                        // tgemm<5>, 126 CTAs
    const int AGG_BLK = (N_NODES + NPC - 1) / NPC;  // 1250
    const float* fnull = nullptr;

    // layer 0 inputs: xa(fp16),xb(fp16),t1(fp32) from x0(fp16)
    cfg4.gridDim = gG3;
    cudaLaunchKernelEx(&cfg4, tgemm<4>, (const __half*)px,
                       (const __half*)pwt, 0, 1, 2,
                       fnull, fnull, fnull, fnull, fnull, fnull,
                       pxa, pxb, pt1, (int)N_NODES, 256, 16 | 32);

    // join CSR + vbias pipeline before first aggregate
    cudaStreamWaitEvent(0, evB, 0);

    for (int l = 0; l < NLAYERS; l++) {
        const float* W1c = mw1 + (size_t)l * 518 * HID + 512 * HID;

        // ragg16[n] = fp16( sum relu(xa16[src]+xb16[n]+ef@W1c+b1) )
        cfgA.gridDim = dim3(AGG_BLK, 1, 1);
        cudaLaunchKernelEx(&cfgA, aggregate_kernel, (const __half2*)pxa,
                           (const __half2*)pxb, W1c,
                           (const float*)(mb1 + (size_t)l * HID),
                           (__half2*)pagg);

        // h(fp16) = relu(ragg@(W2@U1b) + deg*(b2@U1b) + ub1 + t1)
        cfg5.gridDim = gS;
        cudaLaunchKernelEx(&cfg5, tgemm<5>, (const __half*)pagg,
                           (const __half*)pwt, 3 + l, 0, 0,
                           (const float*)(ub1 + (size_t)l * HID), fnull, fnull,
                           (const float*)(pvb + (size_t)l * 256),
                           (const float*)pdegf, (const float*)pt1,
                           ph, (float*)nullptr, (float*)nullptr,
                           (int)N_NODES, 256, 1 | 2 | 4 | 8 | 16);

        if (l < NLAYERS - 1) {
            // next xa(fp16),xb(fp16),t1(fp32) from h(fp16), combined weights
            int cb = 6 + 3 * l;
            cfg4.gridDim = gG3;
            cudaLaunchKernelEx(&cfg4, tgemm<4>, (const __half*)ph,
                               (const __half*)pwt,
                               9 + 3 * l, 10 + 3 * l, 11 + 3 * l,
                               (const float*)(pvb + (size_t)cb * 256),
                               (const float*)(pvb + (size_t)(cb + 1) * 256),
                               (const float*)(pvb + (size_t)(cb + 2) * 256),
                               fnull, fnull, fnull,
                               pxa, pxb, pt1, (int)N_NODES, 256, 4 | 16 | 32);
        }
    }

    // readout r1(fp16) = relu(h@(U2_5@rw1) + (ub2_5@rw1 + rb1))
    cfg5.gridDim = gS;
    cudaLaunchKernelEx(&cfg5, tgemm<5>, (const __half*)ph,
                       (const __half*)pwt, 24, 0, 0,
                       (const float*)(pvb + (size_t)21 * 256), fnull, fnull,
                       fnull, fnull, fnull,
                       pt1, (float*)nullptr, (float*)nullptr,
                       (int)N_NODES, 256, 1 | 4 | 16);
    // r2 fused with readout: out = mean( relu(r1@rw2 + rb2) . rw3 ) + rb3
    cfg5.gridDim = dim3(1, MT5, 1);
    cudaLaunchKernelEx(&cfg5, tgemm<5>, (const __half*)pt1,
                       (const __half*)pwt, 25, 0, 0,
                       rb2, fnull, rb3,
                       rw3, fnull, fnull,
                       (float*)d_out, (float*)nullptr, (float*)nullptr,
                       (int)N_NODES, 128, 1 | 4 | 64);
}